// round 14
// baseline (speedup 1.0000x reference)
#include <cuda_runtime.h>
#include <cuda_bf16.h>
#include <cuda_fp16.h>
#include <math.h>
#include <stdint.h>

#define L_SEQ   2048
#define BATCH   2
#define DMODEL  1024
#define DIN     2048
#define NHEADS  4
#define PDIM    512
#define DSTATE  64
#define DPROJ   4612
#define NPAD_I  4616
#define NROWS   4096   /* BATCH * L_SEQ */
#define VOCAB   32000
#define NLAYERS 4
#define NCHUNK  64
#define TCH     32
#define EPS_RMS 1.1920929e-07f

// ---------------- scratch (__device__ globals: alloc-free) ----------------
__device__ float g_H   [NROWS * DMODEL];
__device__ float g_Hres[NROWS * DMODEL];
__device__ float g_zx  [NROWS * DPROJ];
__device__ float g_cumA[NROWS * NHEADS];
__device__ float g_ylocal[NROWS * DIN];
__device__ float g_S[BATCH * NHEADS * NCHUNK * DSTATE * PDIM];
__device__ __align__(16) __nv_bfloat16 g_Ahi[NROWS * DIN];
__device__ __align__(16) __nv_bfloat16 g_Alo[NROWS * DIN];
__device__ __align__(16) __nv_bfloat16 g_WiHi[NLAYERS * DMODEL * NPAD_I];
__device__ __align__(16) __nv_bfloat16 g_WiLo[NLAYERS * DMODEL * NPAD_I];
__device__ __align__(16) __nv_bfloat16 g_WoHi[NLAYERS * DIN * DMODEL];
__device__ __align__(16) __nv_bfloat16 g_WoLo[NLAYERS * DIN * DMODEL];
__device__ __align__(16) __half g_HB[DMODEL * VOCAB];

// ---------------- embedding gather ----------------
__global__ void k_embed(const int* __restrict__ tokens,
                        const float* __restrict__ embed) {
    int row = blockIdx.x;
    int t   = threadIdx.x;
    int tok = tokens[row];
    const float4* src = (const float4*)(embed + (size_t)tok * DMODEL);
    ((float4*)(g_H + (size_t)row * DMODEL))[t] = src[t];
}

// ---------------- all weight splits, one launch ----------------
#define WI_BLKS (NLAYERS * DMODEL * 5)   /* 20480 */
#define WO_BLKS (NLAYERS * DIN)          /* 8192  */
#define HD_BLKS (32 * DMODEL)            /* 32768 */
__global__ void __launch_bounds__(256) k_splitAll(
    const float* __restrict__ Wi, const float* __restrict__ Wo,
    const float* __restrict__ headW)
{
    int id = blockIdx.x, tid = threadIdx.x;
    if (id < WI_BLKS) {
        int l = id / (DMODEL * 5);
        int rem = id % (DMODEL * 5);
        int r = rem / 5, sub = rem % 5;
        int c4 = (sub * 256 + tid) * 4;
        if (c4 >= DPROJ) return;
        float4 v = *(const float4*)(Wi + (size_t)l * DMODEL * DPROJ + (size_t)r * DPROJ + c4);
        __nv_bfloat16 h0 = __float2bfloat16(v.x), h1 = __float2bfloat16(v.y);
        __nv_bfloat16 h2 = __float2bfloat16(v.z), h3 = __float2bfloat16(v.w);
        __nv_bfloat16 l0 = __float2bfloat16(v.x - __bfloat162float(h0));
        __nv_bfloat16 l1 = __float2bfloat16(v.y - __bfloat162float(h1));
        __nv_bfloat16 l2 = __float2bfloat16(v.z - __bfloat162float(h2));
        __nv_bfloat16 l3 = __float2bfloat16(v.w - __bfloat162float(h3));
        size_t o = (size_t)l * DMODEL * NPAD_I + (size_t)r * NPAD_I + c4;
        *(__nv_bfloat162*)(g_WiHi + o)     = __halves2bfloat162(h0, h1);
        *(__nv_bfloat162*)(g_WiHi + o + 2) = __halves2bfloat162(h2, h3);
        *(__nv_bfloat162*)(g_WiLo + o)     = __halves2bfloat162(l0, l1);
        *(__nv_bfloat162*)(g_WiLo + o + 2) = __halves2bfloat162(l2, l3);
    } else if (id < WI_BLKS + WO_BLKS) {
        int id2 = id - WI_BLKS;
        int l = id2 / DIN, r = id2 % DIN;
        int c4 = tid * 4;
        float4 v = *(const float4*)(Wo + (size_t)l * DIN * DMODEL + (size_t)r * DMODEL + c4);
        __nv_bfloat16 h0 = __float2bfloat16(v.x), h1 = __float2bfloat16(v.y);
        __nv_bfloat16 h2 = __float2bfloat16(v.z), h3 = __float2bfloat16(v.w);
        __nv_bfloat16 l0 = __float2bfloat16(v.x - __bfloat162float(h0));
        __nv_bfloat16 l1 = __float2bfloat16(v.y - __bfloat162float(h1));
        __nv_bfloat16 l2 = __float2bfloat16(v.z - __bfloat162float(h2));
        __nv_bfloat16 l3 = __float2bfloat16(v.w - __bfloat162float(h3));
        size_t o = (size_t)l * DIN * DMODEL + (size_t)r * DMODEL + c4;
        *(__nv_bfloat162*)(g_WoHi + o)     = __halves2bfloat162(h0, h1);
        *(__nv_bfloat162*)(g_WoHi + o + 2) = __halves2bfloat162(h2, h3);
        *(__nv_bfloat162*)(g_WoLo + o)     = __halves2bfloat162(l0, l1);
        *(__nv_bfloat162*)(g_WoLo + o + 2) = __halves2bfloat162(l2, l3);
    } else {
        int id3 = id - WI_BLKS - WO_BLKS;
        int r = id3 >> 5, sub = id3 & 31;
        int c4 = (sub * 256 + tid) * 4;
        if (c4 >= VOCAB) return;
        float4 v = *(const float4*)(headW + (size_t)r * VOCAB + c4);
        size_t o = (size_t)r * VOCAB + c4;
        *(__half2*)(g_HB + o)     = __floats2half2_rn(v.x, v.y);
        *(__half2*)(g_HB + o + 2) = __floats2half2_rn(v.z, v.w);
    }
}

// ---------------- fused layer prep: sinkhorn + hres + rms + bf16 split ----------------
__global__ void __launch_bounds__(256) k_pre(const float* __restrict__ logits,
                                             const float* __restrict__ w,
                                             __nv_bfloat16* __restrict__ hi,
                                             __nv_bfloat16* __restrict__ lo) {
    __shared__ float sr[1024];
    __shared__ float sM[16];
    __shared__ float red[8];
    __shared__ float s_scale;
    int row = blockIdx.x, tid = threadIdx.x;
    float4 v = ((const float4*)(g_H + (size_t)row * DMODEL))[tid];
    *(float4*)&sr[tid * 4] = v;
    if (tid == 0) {
        float Mm[16];
        #pragma unroll
        for (int i = 0; i < 16; i++) {
            float s = 1.f / (1.f + expf(-logits[i]));
            Mm[i] = s + (((i >> 2) == (i & 3)) ? 1.f : 0.f);
        }
        for (int it = 0; it < 5; it++) {
            #pragma unroll
            for (int i = 0; i < 4; i++) {
                float s = Mm[i*4+0] + Mm[i*4+1] + Mm[i*4+2] + Mm[i*4+3] + 1e-6f;
                float inv = 1.f / s;
                #pragma unroll
                for (int j = 0; j < 4; j++) Mm[i*4+j] *= inv;
            }
            #pragma unroll
            for (int j = 0; j < 4; j++) {
                float s = Mm[0*4+j] + Mm[1*4+j] + Mm[2*4+j] + Mm[3*4+j] + 1e-6f;
                float inv = 1.f / s;
                #pragma unroll
                for (int i = 0; i < 4; i++) Mm[i*4+j] *= inv;
            }
        }
        #pragma unroll
        for (int i = 0; i < 16; i++) sM[i] = Mm[i];
    }
    float ss = v.x*v.x + v.y*v.y + v.z*v.z + v.w*v.w;
    #pragma unroll
    for (int o = 16; o > 0; o >>= 1) ss += __shfl_xor_sync(0xffffffffu, ss, o);
    if ((tid & 31) == 0) red[tid >> 5] = ss;
    __syncthreads();
    if (tid == 0) {
        float tot = 0.f;
        #pragma unroll
        for (int i = 0; i < 8; i++) tot += red[i];
        s_scale = rsqrtf(tot * (1.0f / DMODEL) + EPS_RMS);
    }
    __syncthreads();
    float sc = s_scale;
    float4 wv = ((const float4*)w)[tid];
    float o0 = v.x*sc*wv.x, o1 = v.y*sc*wv.y, o2 = v.z*sc*wv.z, o3 = v.w*sc*wv.w;
    __nv_bfloat16 h0 = __float2bfloat16(o0), h1 = __float2bfloat16(o1);
    __nv_bfloat16 h2 = __float2bfloat16(o2), h3 = __float2bfloat16(o3);
    __nv_bfloat16 l0 = __float2bfloat16(o0 - __bfloat162float(h0));
    __nv_bfloat16 l1 = __float2bfloat16(o1 - __bfloat162float(h1));
    __nv_bfloat16 l2 = __float2bfloat16(o2 - __bfloat162float(h2));
    __nv_bfloat16 l3 = __float2bfloat16(o3 - __bfloat162float(h3));
    __nv_bfloat162* dh = (__nv_bfloat162*)(hi + (size_t)row * DMODEL);
    __nv_bfloat162* dl = (__nv_bfloat162*)(lo + (size_t)row * DMODEL);
    dh[tid*2]   = __halves2bfloat162(h0, h1);
    dh[tid*2+1] = __halves2bfloat162(h2, h3);
    dl[tid*2]   = __halves2bfloat162(l0, l1);
    dl[tid*2+1] = __halves2bfloat162(l2, l3);
    float hh0 = sr[tid], hh1 = sr[256 + tid], hh2 = sr[512 + tid], hh3 = sr[768 + tid];
    float* o = g_Hres + (size_t)row * DMODEL;
    #pragma unroll
    for (int j = 0; j < 4; j++)
        o[j*256 + tid] = sM[j*4+0]*hh0 + sM[j*4+1]*hh1 + sM[j*4+2]*hh2 + sM[j*4+3]*hh3;
}

// ---------------- RMS norm, fp16 output (head path) ----------------
__global__ void k_rms_f16(const float* __restrict__ w,
                          const float* __restrict__ src,
                          __half* __restrict__ dst) {
    int row = blockIdx.x, tid = threadIdx.x;
    float4 v = ((const float4*)(src + (size_t)row * DMODEL))[tid];
    float ss = v.x*v.x + v.y*v.y + v.z*v.z + v.w*v.w;
    #pragma unroll
    for (int o = 16; o > 0; o >>= 1) ss += __shfl_xor_sync(0xffffffffu, ss, o);
    __shared__ float red[8];
    __shared__ float s_scale;
    if ((tid & 31) == 0) red[tid >> 5] = ss;
    __syncthreads();
    if (tid == 0) {
        float tot = 0.f;
        #pragma unroll
        for (int i = 0; i < 8; i++) tot += red[i];
        s_scale = rsqrtf(tot * (1.0f / DMODEL) + EPS_RMS);
    }
    __syncthreads();
    float sc = s_scale;
    float4 wv = ((const float4*)w)[tid];
    __half2* dh = (__half2*)(dst + (size_t)row * DMODEL);
    dh[tid*2]   = __floats2half2_rn(v.x*sc*wv.x, v.y*sc*wv.y);
    dh[tid*2+1] = __floats2half2_rn(v.z*sc*wv.z, v.w*sc*wv.w);
}

// ---------------- scan phase 1: per-chunk local scan (TCH=32) ----------------
__global__ void __launch_bounds__(64) k_scan1(const float* __restrict__ dt_bias,
                                              const float* __restrict__ A_log, int l) {
    int pblk = blockIdx.x, h = blockIdx.y;
    int b = blockIdx.z >> 6, c = blockIdx.z & 63;
    int tid = threadIdx.x;
    int p = pblk * 64 + tid;
    int t0 = c * TCH;
    float dtb = dt_bias[l*NHEADS + h];
    float Ah  = -expf(A_log[l*NHEADS + h]);
    __shared__ float sBC[2][128];
    float hs[64];
    #pragma unroll
    for (int n = 0; n < 64; n++) hs[n] = 0.f;
    float P = 1.f;

    float nb0, nb1, nx, ndt, ndA;
    {
        size_t r0 = (size_t)(b * L_SEQ + t0) * DPROJ;
        nb0 = g_zx[r0 + 2*DIN + NHEADS + h*128 + tid];
        nb1 = g_zx[r0 + 2*DIN + NHEADS + h*128 + 64 + tid];
        nx  = g_zx[r0 + DIN + h*PDIM + p];
        float v = g_zx[r0 + 2*DIN + h] + dtb;
        ndt = fmaxf(v, 0.f) + log1pf(expf(-fabsf(v)));
        ndA = expf(ndt * Ah);
    }
    sBC[0][tid] = nb0; sBC[0][64 + tid] = nb1;
    __syncthreads();

    for (int i = 0; i < TCH; i++) {
        int t = t0 + i;
        int buf = i & 1;
        float cx = nx, cdt = ndt, cdA = ndA;
        if (i + 1 < TCH) {
            size_t r1 = (size_t)(b * L_SEQ + t + 1) * DPROJ;
            nb0 = g_zx[r1 + 2*DIN + NHEADS + h*128 + tid];
            nb1 = g_zx[r1 + 2*DIN + NHEADS + h*128 + 64 + tid];
            nx  = g_zx[r1 + DIN + h*PDIM + p];
            float v = g_zx[r1 + 2*DIN + h] + dtb;
            ndt = fmaxf(v, 0.f) + log1pf(expf(-fabsf(v)));
            ndA = expf(ndt * Ah);
        }
        float ux = cdt * cx;
        float y0 = 0.f, y1 = 0.f, y2a = 0.f, y3 = 0.f;
        #pragma unroll
        for (int n4 = 0; n4 < 16; n4++) {
            float4 Bq = *(const float4*)&sBC[buf][n4 * 4];
            float4 Cq = *(const float4*)&sBC[buf][64 + n4 * 4];
            hs[n4*4+0] = fmaf(hs[n4*4+0], cdA, Bq.x * ux);
            hs[n4*4+1] = fmaf(hs[n4*4+1], cdA, Bq.y * ux);
            hs[n4*4+2] = fmaf(hs[n4*4+2], cdA, Bq.z * ux);
            hs[n4*4+3] = fmaf(hs[n4*4+3], cdA, Bq.w * ux);
            y0  = fmaf(Cq.x, hs[n4*4+0], y0);
            y1  = fmaf(Cq.y, hs[n4*4+1], y1);
            y2a = fmaf(Cq.z, hs[n4*4+2], y2a);
            y3  = fmaf(Cq.w, hs[n4*4+3], y3);
        }
        P *= cdA;
        if (pblk == 0 && tid == 0)
            g_cumA[(b * L_SEQ + t) * NHEADS + h] = P;
        g_ylocal[(size_t)(b * L_SEQ + t) * DIN + h * PDIM + p] =
            (y0 + y1) + (y2a + y3);
        sBC[buf ^ 1][tid] = nb0;
        sBC[buf ^ 1][64 + tid] = nb1;
        __syncthreads();
    }
    size_t sb = ((size_t)((b * NHEADS + h) * NCHUNK + c)) * DSTATE * PDIM;
    #pragma unroll
    for (int n = 0; n < 64; n++)
        g_S[sb + n * PDIM + p] = hs[n];
}

// ---------------- scan phase 2: inter-chunk recurrence (in place) ----------------
__global__ void k_scan2() {
    int bh = blockIdx.x;
    int b = bh >> 2, h = bh & 3;
    int idx = blockIdx.y * 256 + threadIdx.x;
    int n = idx >> 9, p = idx & 511;
    size_t base = ((size_t)bh * NCHUNK) * DSTATE * PDIM + n * PDIM + p;
    float prev = 0.f;
    for (int c = 0; c < NCHUNK; c++) {
        float Q = g_cumA[(b * L_SEQ + c * TCH + TCH - 1) * NHEADS + h];
        size_t o = base + (size_t)c * DSTATE * PDIM;
        float s = g_S[o];
        g_S[o] = prev;
        prev = fmaf(Q, prev, s);
    }
}

// ---------------- scan phase 3: correction + epilogue + bf16 split (TCH=32) ----------------
__global__ void __launch_bounds__(256) k_scan3(const float* __restrict__ Dp, int l) {
    int c = blockIdx.x, h = blockIdx.y, b = blockIdx.z;
    int tid = threadIdx.x;
    __shared__ float sC[TCH][65];
    __shared__ float sP[TCH];
    __shared__ float shin[64][128];
    #pragma unroll
    for (int i = 0; i < (TCH * 64) / 256; i++) {
        int e = tid + i * 256;
        int t = e >> 6, n = e & 63;
        int row = b * L_SEQ + c * TCH + t;
        sC[t][n] = g_zx[(size_t)row * DPROJ + 2*DIN + NHEADS + h*128 + 64 + n];
    }
    if (tid < TCH)
        sP[tid] = g_cumA[(b * L_SEQ + c * TCH + tid) * NHEADS + h];
    float Dh = Dp[l * NHEADS + h];
    __syncthreads();

    size_t hb = ((size_t)((b * NHEADS + h) * NCHUNK + c)) * DSTATE * PDIM;
    int pl = tid & 127, tb = (tid >> 7) * (TCH / 2);
    #pragma unroll
    for (int pt = 0; pt < 4; pt++) {
        int p0 = pt * 128;
        #pragma unroll
        for (int i = 0; i < 32; i++) {
            int e = tid + i * 256;
            int n = e >> 7, pp = e & 127;
            shin[n][pp] = g_S[hb + n * PDIM + p0 + pp];
        }
        __syncthreads();
        int p = p0 + pl;
        for (int tt = 0; tt < TCH / 2; tt++) {
            int t = tb + tt;
            float a0 = 0.f, a1 = 0.f;
            #pragma unroll
            for (int n = 0; n < 64; n += 2) {
                a0 = fmaf(sC[t][n],   shin[n][pl],   a0);
                a1 = fmaf(sC[t][n+1], shin[n+1][pl], a1);
            }
            int row = b * L_SEQ + c * TCH + t;
            size_t zo = (size_t)row * DPROJ;
            float x = g_zx[zo + DIN + h*PDIM + p];
            float z = g_zx[zo + h*PDIM + p];
            float yl = g_ylocal[(size_t)row * DIN + h*PDIM + p];
            float y = yl + sP[t] * (a0 + a1) + x * Dh;
            float sig = 1.f / (1.f + expf(-z));
            float out = y * (z * sig);
            size_t oi = (size_t)row * DIN + h * PDIM + p;
            __nv_bfloat16 oh = __float2bfloat16(out);
            g_Ahi[oi] = oh;
            g_Alo[oi] = __float2bfloat16(out - __bfloat162float(oh));
        }
        __syncthreads();
    }
}

// ================= shared GEMM helpers =================
#define KT      32
#define ASTRIDE (KT + 8)               /* 40 elems */
#define STAGE_A (128 * ASTRIDE)        /* 5120 elems */
#define GBN     128
#define GBSTR   (GBN + 8)              /* 136 */
#define GSTB    (KT * GBSTR)           /* 4352 elems */

__device__ __forceinline__ uint32_t smem_u32(const void* p) {
    return (uint32_t)__cvta_generic_to_shared(p);
}
__device__ __forceinline__ void cp16(uint32_t dst, const void* src) {
    asm volatile("cp.async.cg.shared.global [%0],[%1],16;\n" :: "r"(dst), "l"(src));
}
__device__ __forceinline__ void cp16z(uint32_t dst, const void* src, int bytes) {
    asm volatile("cp.async.cg.shared.global [%0],[%1],16,%2;\n" :: "r"(dst), "l"(src), "r"(bytes));
}
template<int G>
__device__ __forceinline__ void wgroup() {
    asm volatile("cp.async.wait_group %0;\n" :: "n"(G));
}
__device__ __forceinline__ void ldsm_x4(uint32_t* r, uint32_t a) {
    asm volatile("ldmatrix.sync.aligned.m8n8.x4.shared.b16 {%0,%1,%2,%3}, [%4];\n"
        : "=r"(r[0]), "=r"(r[1]), "=r"(r[2]), "=r"(r[3]) : "r"(a));
}
__device__ __forceinline__ void ldsm_x4t(uint32_t* r, uint32_t a) {
    asm volatile("ldmatrix.sync.aligned.m8n8.x4.trans.shared.b16 {%0,%1,%2,%3}, [%4];\n"
        : "=r"(r[0]), "=r"(r[1]), "=r"(r[2]), "=r"(r[3]) : "r"(a));
}
__device__ __forceinline__ void mma_bf16(float* c, const uint32_t* a, const uint32_t* b) {
    asm volatile(
        "mma.sync.aligned.m16n8k16.row.col.f32.bf16.bf16.f32 "
        "{%0,%1,%2,%3}, {%4,%5,%6,%7}, {%8,%9}, {%0,%1,%2,%3};\n"
        : "+f"(c[0]), "+f"(c[1]), "+f"(c[2]), "+f"(c[3])
        : "r"(a[0]), "r"(a[1]), "r"(a[2]), "r"(a[3]), "r"(b[0]), "r"(b[1]));
}
__device__ __forceinline__ void mma_f16(float* c, const uint32_t* a, const uint32_t* b) {
    asm volatile(
        "mma.sync.aligned.m16n8k16.row.col.f32.f16.f16.f32 "
        "{%0,%1,%2,%3}, {%4,%5,%6,%7}, {%8,%9}, {%0,%1,%2,%3};\n"
        : "+f"(c[0]), "+f"(c[1]), "+f"(c[2]), "+f"(c[3])
        : "r"(a[0]), "r"(a[1]), "r"(a[2]), "r"(a[3]), "r"(b[0]), "r"(b[1]));
}

// ================= bf16x3 GEMM (layers): 128x128 tile, 3 stages, 2 CTAs/SM =================
#define GSTAGES 3
#define GSELEMS (2*STAGE_A + 2*GSTB)           /* 18944 elems */
#define GSMEM   (GSTAGES * GSELEMS * 2)        /* 113664 B */

template<bool NGUARD>
__device__ __forceinline__ void load_stage(
    __nv_bfloat16* sb,
    const __nv_bfloat16* __restrict__ Ahi, const __nv_bfloat16* __restrict__ Alo,
    const __nv_bfloat16* __restrict__ Bhi, const __nv_bfloat16* __restrict__ Blo,
    int row0, int col0, int k0, int N, int Nld, int K, int tid)
{
    #pragma unroll
    for (int i = 0; i < 2; i++) {
        int c  = tid * 2 + i;
        int r  = c >> 2;
        int kc = (c & 3) * 8;
        size_t go = (size_t)(row0 + r) * K + k0 + kc;
        cp16(smem_u32(sb + r * ASTRIDE + kc),            Ahi + go);
        cp16(smem_u32(sb + STAGE_A + r * ASTRIDE + kc),  Alo + go);
    }
    #pragma unroll
    for (int i = 0; i < 2; i++) {
        int c   = tid + i * 256;
        int r   = c >> 4;
        int nc  = (c & 15) * 8;
        int col = col0 + nc;
        size_t go = (size_t)(k0 + r) * Nld + col;
        uint32_t dH = smem_u32(sb + 2*STAGE_A + r * GBSTR + nc);
        uint32_t dL = smem_u32(sb + 2*STAGE_A + GSTB + r * GBSTR + nc);
        if (!NGUARD) {
            cp16(dH, Bhi + go);
            cp16(dL, Blo + go);
        } else {
            int rem = N - col;
            if (rem >= 8) {
                cp16(dH, Bhi + go);
                cp16(dL, Blo + go);
            } else if (rem > 0) {
                cp16z(dH, Bhi + go, rem * 2);
                cp16z(dL, Blo + go, rem * 2);
            } else {
                uint4 z = make_uint4(0, 0, 0, 0);
                *(uint4*)(sb + 2*STAGE_A + r * GBSTR + nc) = z;
                *(uint4*)(sb + 2*STAGE_A + GSTB + r * GBSTR + nc) = z;
            }
        }
    }
}

template <bool RES>
__global__ void __launch_bounds__(256, 2) k_gemm3(
    const __nv_bfloat16* __restrict__ Ahi, const __nv_bfloat16* __restrict__ Alo,
    const __nv_bfloat16* __restrict__ Bhi, const __nv_bfloat16* __restrict__ Blo,
    const float* __restrict__ bias, const float* __restrict__ Rs,
    float* __restrict__ C, int M, int N, int Nld, int K)
{
    extern __shared__ __nv_bfloat16 smem[];
    int tid  = threadIdx.x;
    int row0 = blockIdx.x * 128, col0 = blockIdx.y * GBN;
    bool nguard = (col0 + GBN > N);
    int ktiles = K / KT;

    #pragma unroll
    for (int s = 0; s < GSTAGES - 1; s++) {
        __nv_bfloat16* sb = smem + s * GSELEMS;
        if (nguard) load_stage<true >(sb, Ahi, Alo, Bhi, Blo, row0, col0, s*KT, N, Nld, K, tid);
        else        load_stage<false>(sb, Ahi, Alo, Bhi, Blo, row0, col0, s*KT, N, Nld, K, tid);
        asm volatile("cp.async.commit_group;\n");
    }

    int lane = tid & 31, wid = tid >> 5;
    int wm = (wid & 1) * 64, wn = (wid >> 1) * 32;
    int a_r = lane & 15, a_c = (lane >> 4) * 8;
    int l8 = lane & 7, mat = lane >> 3;
    int brow = (mat & 1) * 8 + l8;
    int bcol = (mat >> 1) * 8;

    float acc[4][4][4];
    #pragma unroll
    for (int mt = 0; mt < 4; mt++)
        #pragma unroll
        for (int nt = 0; nt < 4; nt++)
            #pragma unroll
            for (int q = 0; q < 4; q++) acc[mt][nt][q] = 0.f;

    for (int kt = 0; kt < ktiles; kt++) {
        int rem = ktiles - 1 - kt;
        if (rem >= 1) wgroup<1>();
        else          wgroup<0>();
        __syncthreads();
        if (kt + GSTAGES - 1 < ktiles) {
            __nv_bfloat16* sb = smem + ((kt + GSTAGES - 1) % GSTAGES) * GSELEMS;
            int k0 = (kt + GSTAGES - 1) * KT;
            if (nguard) load_stage<true >(sb, Ahi, Alo, Bhi, Blo, row0, col0, k0, N, Nld, K, tid);
            else        load_stage<false>(sb, Ahi, Alo, Bhi, Blo, row0, col0, k0, N, Nld, K, tid);
            asm volatile("cp.async.commit_group;\n");
        }
        __nv_bfloat16* sb = smem + (kt % GSTAGES) * GSELEMS;
        __nv_bfloat16* sbB = sb + 2*STAGE_A;
        #pragma unroll
        for (int ks = 0; ks < 2; ks++) {
            uint32_t afh[4][4], afl[4][4];
            #pragma unroll
            for (int mt = 0; mt < 4; mt++) {
                int r = wm + mt*16 + a_r;
                ldsm_x4(afh[mt], smem_u32(sb + r*ASTRIDE + ks*16 + a_c));
                ldsm_x4(afl[mt], smem_u32(sb + STAGE_A + r*ASTRIDE + ks*16 + a_c));
            }
            #pragma unroll
            for (int np = 0; np < 2; np++) {
                uint32_t bh[4], bl[4];
                int boff = (ks*16 + brow)*GBSTR + wn + np*16 + bcol;
                ldsm_x4t(bh, smem_u32(sbB + boff));
                ldsm_x4t(bl, smem_u32(sbB + GSTB + boff));
                #pragma unroll
                for (int mt = 0; mt < 4; mt++) {
                    mma_bf16(acc[mt][np*2],   afh[mt], bh);
                    mma_bf16(acc[mt][np*2],   afh[mt], bl);
                    mma_bf16(acc[mt][np*2],   afl[mt], bh);
                    mma_bf16(acc[mt][np*2+1], afh[mt], bh + 2);
                    mma_bf16(acc[mt][np*2+1], afh[mt], bl + 2);
                    mma_bf16(acc[mt][np*2+1], afl[mt], bh + 2);
                }
            }
        }
    }

    #pragma unroll
    for (int mt = 0; mt < 4; mt++) {
        int r0 = row0 + wm + mt*16 + (lane >> 2);
        int r1 = r0 + 8;
        #pragma unroll
        for (int nt = 0; nt < 4; nt++) {
            int c0 = col0 + wn + nt*8 + (lane & 3)*2;
            float* a = acc[mt][nt];
            if (c0 < N) {
                float v0 = a[0] + bias[c0];
                float v2 = a[2] + bias[c0];
                if (RES) { v0 += Rs[(size_t)r0*N + c0]; v2 += Rs[(size_t)r1*N + c0]; }
                C[(size_t)r0*N + c0] = v0;
                C[(size_t)r1*N + c0] = v2;
            }
            if (c0 + 1 < N) {
                float v1 = a[1] + bias[c0+1];
                float v3 = a[3] + bias[c0+1];
                if (RES) { v1 += Rs[(size_t)r0*N + c0+1]; v3 += Rs[(size_t)r1*N + c0+1]; }
                C[(size_t)r0*N + c0+1] = v1;
                C[(size_t)r1*N + c0+1] = v3;
            }
        }
    }
}

// ================= fp16x1 GEMM (head): 128x128 tile, 4 stages, 2 CTAs/SM =================
#define HSTAGES 4
#define HSELEMS (STAGE_A + GSTB)             /* 9472 elems */
#define HSMEM   (HSTAGES * HSELEMS * 2)      /* 75776 B */

__device__ __forceinline__ void load_stage_h(
    __half* sb,
    const __half* __restrict__ A, const __half* __restrict__ B,
    int row0, int col0, int k0, int N, int K, int tid)
{
    #pragma unroll
    for (int i = 0; i < 2; i++) {
        int c  = tid * 2 + i;
        int r  = c >> 2;
        int kc = (c & 3) * 8;
        cp16(smem_u32(sb + r * ASTRIDE + kc), A + (size_t)(row0 + r) * K + k0 + kc);
    }
    #pragma unroll
    for (int i = 0; i < 2; i++) {
        int c   = tid + i * 256;
        int r   = c >> 4;
        int nc  = (c & 15) * 8;
        size_t go = (size_t)(k0 + r) * N + col0 + nc;
        cp16(smem_u32(sb + STAGE_A + r * GBSTR + nc), B + go);
    }
}

__global__ void __launch_bounds__(256, 2) k_gemm1h(
    const __half* __restrict__ A, const __half* __restrict__ B,
    const float* __restrict__ bias,
    float* __restrict__ C, int M, int N, int K)
{
    extern __shared__ __half hsmem[];
    int tid  = threadIdx.x;
    int row0 = blockIdx.x * 128, col0 = blockIdx.y * GBN;
    int ktiles = K / KT;

    #pragma unroll
    for (int s = 0; s < HSTAGES - 1; s++) {
        load_stage_h(hsmem + s * HSELEMS, A, B, row0, col0, s*KT, N, K, tid);
        asm volatile("cp.async.commit_group;\n");
    }

    int lane = tid & 31, wid = tid >> 5;
    int wm = (wid & 1) * 64, wn = (wid >> 1) * 32;
    int a_r = lane & 15, a_c = (lane >> 4) * 8;
    int l8 = lane & 7, mat = lane >> 3;
    int brow = (mat & 1) * 8 + l8;
    int bcol = (mat >> 1) * 8;

    float acc[4][4][4];
    #pragma unroll
    for (int mt = 0; mt < 4; mt++)
        #pragma unroll
        for (int nt = 0; nt < 4; nt++)
            #pragma unroll
            for (int q = 0; q < 4; q++) acc[mt][nt][q] = 0.f;

    for (int kt = 0; kt < ktiles; kt++) {
        int rem = ktiles - 1 - kt;
        if (rem >= 2)      wgroup<2>();
        else if (rem == 1) wgroup<1>();
        else               wgroup<0>();
        __syncthreads();
        if (kt + HSTAGES - 1 < ktiles) {
            load_stage_h(hsmem + ((kt + HSTAGES - 1) % HSTAGES) * HSELEMS,
                         A, B, row0, col0, (kt + HSTAGES - 1) * KT, N, K, tid);
            asm volatile("cp.async.commit_group;\n");
        }
        __half* sb  = hsmem + (kt % HSTAGES) * HSELEMS;
        __half* sbB = sb + STAGE_A;
        #pragma unroll
        for (int ks = 0; ks < 2; ks++) {
            uint32_t af[4][4];
            #pragma unroll
            for (int mt = 0; mt < 4; mt++) {
                int r = wm + mt*16 + a_r;
                ldsm_x4(af[mt], smem_u32(sb + r*ASTRIDE + ks*16 + a_c));
            }
            #pragma unroll
            for (int np = 0; np < 2; np++) {
                uint32_t bb[4];
                int boff = (ks*16 + brow)*GBSTR + wn + np*16 + bcol;
                ldsm_x4t(bb, smem_u32(sbB + boff));
                #pragma unroll
                for (int mt = 0; mt < 4; mt++) {
                    mma_f16(acc[mt][np*2],   af[mt], bb);
                    mma_f16(acc[mt][np*2+1], af[mt], bb + 2);
                }
            }
        }
    }

    #pragma unroll
    for (int mt = 0; mt < 4; mt++) {
        int r0 = row0 + wm + mt*16 + (lane >> 2);
        int r1 = r0 + 8;
        #pragma unroll
        for (int nt = 0; nt < 4; nt++) {
            int c0 = col0 + wn + nt*8 + (lane & 3)*2;
            float* a = acc[mt][nt];
            float b0 = bias[c0], b1 = bias[c0+1];
            C[(size_t)r0*N + c0]     = a[0] + b0;
            C[(size_t)r0*N + c0 + 1] = a[1] + b1;
            C[(size_t)r1*N + c0]     = a[2] + b0;
            C[(size_t)r1*N + c0 + 1] = a[3] + b1;
        }
    }
}

// ---------------- host orchestration ----------------
extern "C" void kernel_launch(void* const* d_in, const int* in_sizes, int n_in,
                              void* d_out, int out_size) {
    const int*   tokens  = (const int*)  d_in[0];
    const float* embed   = (const float*)d_in[1];
    const float* norm_w  = (const float*)d_in[2];
    const float* Wi      = (const float*)d_in[3];
    const float* bi      = (const float*)d_in[4];
    const float* A_log   = (const float*)d_in[5];
    const float* Dp      = (const float*)d_in[6];
    const float* dt_bias = (const float*)d_in[7];
    const float* Wo      = (const float*)d_in[8];
    const float* bo      = (const float*)d_in[9];
    const float* mixl    = (const float*)d_in[10];
    const float* norm_f  = (const float*)d_in[11];
    const float* headW   = (const float*)d_in[12];
    const float* headb   = (const float*)d_in[13];
    float* out = (float*)d_out;

    cudaFuncSetAttribute((const void*)k_gemm3<false>, cudaFuncAttributeMaxDynamicSharedMemorySize, GSMEM);
    cudaFuncSetAttribute((const void*)k_gemm3<true >, cudaFuncAttributeMaxDynamicSharedMemorySize, GSMEM);
    cudaFuncSetAttribute((const void*)k_gemm1h,       cudaFuncAttributeMaxDynamicSharedMemorySize, HSMEM);

    void *pH, *pHres, *pzx, *pAhi, *pAlo, *pWiHi, *pWiLo, *pWoHi, *pWoLo, *pHB;
    cudaGetSymbolAddress(&pH,    g_H);
    cudaGetSymbolAddress(&pHres, g_Hres);
    cudaGetSymbolAddress(&pzx,   g_zx);
    cudaGetSymbolAddress(&pAhi,  g_Ahi);
    cudaGetSymbolAddress(&pAlo,  g_Alo);
    cudaGetSymbolAddress(&pWiHi, g_WiHi);
    cudaGetSymbolAddress(&pWiLo, g_WiLo);
    cudaGetSymbolAddress(&pWoHi, g_WoHi);
    cudaGetSymbolAddress(&pWoLo, g_WoLo);
    cudaGetSymbolAddress(&pHB,   g_HB);
    float* fH    = (float*)pH;
    float* fHres = (float*)pHres;
    float* fzx   = (float*)pzx;
    __nv_bfloat16* Ahi  = (__nv_bfloat16*)pAhi;
    __nv_bfloat16* Alo  = (__nv_bfloat16*)pAlo;
    __nv_bfloat16* WiHi = (__nv_bfloat16*)pWiHi;
    __nv_bfloat16* WiLo = (__nv_bfloat16*)pWiLo;
    __nv_bfloat16* WoHi = (__nv_bfloat16*)pWoHi;
    __nv_bfloat16* WoLo = (__nv_bfloat16*)pWoLo;
    __half* hB = (__half*)pHB;
    __half* hA = (__half*)pAhi;   // head A reuses g_Ahi storage as fp16

    k_embed<<<NROWS, 256>>>(tokens, embed);
    k_splitAll<<<WI_BLKS + WO_BLKS + HD_BLKS, 256>>>(Wi, Wo, headW);

    for (int l = 0; l < NLAYERS; l++) {
        k_pre<<<NROWS, 256>>>(mixl + l * 16, norm_w + (size_t)l * DMODEL, Ahi, Alo);
        k_gemm3<false><<<dim3(NROWS / 128, (DPROJ + GBN - 1) / GBN), 256, GSMEM>>>(
            Ahi, Alo,
            WiHi + (size_t)l * DMODEL * NPAD_I, WiLo + (size_t)l * DMODEL * NPAD_I,
            bi + (size_t)l * DPROJ, nullptr,
            fzx, NROWS, DPROJ, NPAD_I, DMODEL);
        k_scan1<<<dim3(8, NHEADS, BATCH * NCHUNK), 64>>>(dt_bias, A_log, l);
        k_scan2<<<dim3(BATCH * NHEADS, 128), 256>>>();
        k_scan3<<<dim3(NCHUNK, NHEADS, BATCH), 256>>>(Dp, l);
        k_gemm3<true><<<dim3(NROWS / 128, DMODEL / GBN), 256, GSMEM>>>(
            Ahi, Alo,
            WoHi + (size_t)l * DIN * DMODEL, WoLo + (size_t)l * DIN * DMODEL,
            bo + (size_t)l * DMODEL, fHres,
            fH, NROWS, DMODEL, DMODEL, DIN);
    }

    // head: plain fp16 (A fp16, B fp16 single) — 1 mma per tile pair
    k_rms_f16<<<NROWS, 256>>>(norm_f, fH, hA);
    k_gemm1h<<<dim3(NROWS / 128, VOCAB / GBN), 256, HSMEM>>>(
        hA, hB, headb, out, NROWS, VOCAB, DMODEL);
}

// round 15
// speedup vs baseline: 1.1383x; 1.1383x over previous
#include <cuda_runtime.h>
#include <cuda_bf16.h>
#include <cuda_fp16.h>
#include <math.h>
#include <stdint.h>

#define L_SEQ   2048
#define BATCH   2
#define DMODEL  1024
#define DIN     2048
#define NHEADS  4
#define PDIM    512
#define DSTATE  64
#define DPROJ   4612
#define NPAD_I  4616
#define NROWS   4096   /* BATCH * L_SEQ */
#define VOCAB   32000
#define NLAYERS 4
#define NCHUNK  32
#define TCH     64
#define EPS_RMS 1.1920929e-07f

// ---------------- scratch (__device__ globals: alloc-free) ----------------
__device__ float g_H   [NROWS * DMODEL];
__device__ float g_Hres[NROWS * DMODEL];
__device__ float g_zx  [NROWS * DPROJ];
__device__ float g_cumA[NROWS * NHEADS];
__device__ float g_ylocal[NROWS * DIN];
__device__ float g_S[BATCH * NHEADS * NCHUNK * DSTATE * PDIM];
__device__ __align__(16) __nv_bfloat16 g_Ahi[NROWS * DIN];
__device__ __align__(16) __nv_bfloat16 g_Alo[NROWS * DIN];
__device__ __align__(16) __nv_bfloat16 g_WiHi[NLAYERS * DMODEL * NPAD_I];
__device__ __align__(16) __nv_bfloat16 g_WiLo[NLAYERS * DMODEL * NPAD_I];
__device__ __align__(16) __nv_bfloat16 g_WoHi[NLAYERS * DIN * DMODEL];
__device__ __align__(16) __nv_bfloat16 g_WoLo[NLAYERS * DIN * DMODEL];
__device__ __align__(16) __half g_HB[DMODEL * VOCAB];

// ---------------- embedding gather ----------------
__global__ void k_embed(const int* __restrict__ tokens,
                        const float* __restrict__ embed) {
    int row = blockIdx.x;
    int t   = threadIdx.x;
    int tok = tokens[row];
    const float4* src = (const float4*)(embed + (size_t)tok * DMODEL);
    ((float4*)(g_H + (size_t)row * DMODEL))[t] = src[t];
}

// ---------------- all weight splits, one launch ----------------
#define WI_BLKS (NLAYERS * DMODEL * 5)   /* 20480 */
#define WO_BLKS (NLAYERS * DIN)          /* 8192  */
#define HD_BLKS (32 * DMODEL)            /* 32768 */
__global__ void __launch_bounds__(256) k_splitAll(
    const float* __restrict__ Wi, const float* __restrict__ Wo,
    const float* __restrict__ headW)
{
    int id = blockIdx.x, tid = threadIdx.x;
    if (id < WI_BLKS) {
        int l = id / (DMODEL * 5);
        int rem = id % (DMODEL * 5);
        int r = rem / 5, sub = rem % 5;
        int c4 = (sub * 256 + tid) * 4;
        if (c4 >= DPROJ) return;
        float4 v = *(const float4*)(Wi + (size_t)l * DMODEL * DPROJ + (size_t)r * DPROJ + c4);
        __nv_bfloat16 h0 = __float2bfloat16(v.x), h1 = __float2bfloat16(v.y);
        __nv_bfloat16 h2 = __float2bfloat16(v.z), h3 = __float2bfloat16(v.w);
        __nv_bfloat16 l0 = __float2bfloat16(v.x - __bfloat162float(h0));
        __nv_bfloat16 l1 = __float2bfloat16(v.y - __bfloat162float(h1));
        __nv_bfloat16 l2 = __float2bfloat16(v.z - __bfloat162float(h2));
        __nv_bfloat16 l3 = __float2bfloat16(v.w - __bfloat162float(h3));
        size_t o = (size_t)l * DMODEL * NPAD_I + (size_t)r * NPAD_I + c4;
        *(__nv_bfloat162*)(g_WiHi + o)     = __halves2bfloat162(h0, h1);
        *(__nv_bfloat162*)(g_WiHi + o + 2) = __halves2bfloat162(h2, h3);
        *(__nv_bfloat162*)(g_WiLo + o)     = __halves2bfloat162(l0, l1);
        *(__nv_bfloat162*)(g_WiLo + o + 2) = __halves2bfloat162(l2, l3);
    } else if (id < WI_BLKS + WO_BLKS) {
        int id2 = id - WI_BLKS;
        int l = id2 / DIN, r = id2 % DIN;
        int c4 = tid * 4;
        float4 v = *(const float4*)(Wo + (size_t)l * DIN * DMODEL + (size_t)r * DMODEL + c4);
        __nv_bfloat16 h0 = __float2bfloat16(v.x), h1 = __float2bfloat16(v.y);
        __nv_bfloat16 h2 = __float2bfloat16(v.z), h3 = __float2bfloat16(v.w);
        __nv_bfloat16 l0 = __float2bfloat16(v.x - __bfloat162float(h0));
        __nv_bfloat16 l1 = __float2bfloat16(v.y - __bfloat162float(h1));
        __nv_bfloat16 l2 = __float2bfloat16(v.z - __bfloat162float(h2));
        __nv_bfloat16 l3 = __float2bfloat16(v.w - __bfloat162float(h3));
        size_t o = (size_t)l * DIN * DMODEL + (size_t)r * DMODEL + c4;
        *(__nv_bfloat162*)(g_WoHi + o)     = __halves2bfloat162(h0, h1);
        *(__nv_bfloat162*)(g_WoHi + o + 2) = __halves2bfloat162(h2, h3);
        *(__nv_bfloat162*)(g_WoLo + o)     = __halves2bfloat162(l0, l1);
        *(__nv_bfloat162*)(g_WoLo + o + 2) = __halves2bfloat162(l2, l3);
    } else {
        int id3 = id - WI_BLKS - WO_BLKS;
        int r = id3 >> 5, sub = id3 & 31;
        int c4 = (sub * 256 + tid) * 4;
        if (c4 >= VOCAB) return;
        float4 v = *(const float4*)(headW + (size_t)r * VOCAB + c4);
        size_t o = (size_t)r * VOCAB + c4;
        *(__half2*)(g_HB + o)     = __floats2half2_rn(v.x, v.y);
        *(__half2*)(g_HB + o + 2) = __floats2half2_rn(v.z, v.w);
    }
}

// ---------------- fused layer prep: sinkhorn + hres + rms + bf16 split ----------------
__global__ void __launch_bounds__(256) k_pre(const float* __restrict__ logits,
                                             const float* __restrict__ w,
                                             __nv_bfloat16* __restrict__ hi,
                                             __nv_bfloat16* __restrict__ lo) {
    __shared__ float sr[1024];
    __shared__ float sM[16];
    __shared__ float red[8];
    __shared__ float s_scale;
    int row = blockIdx.x, tid = threadIdx.x;
    float4 v = ((const float4*)(g_H + (size_t)row * DMODEL))[tid];
    *(float4*)&sr[tid * 4] = v;
    if (tid == 0) {
        float Mm[16];
        #pragma unroll
        for (int i = 0; i < 16; i++) {
            float s = 1.f / (1.f + expf(-logits[i]));
            Mm[i] = s + (((i >> 2) == (i & 3)) ? 1.f : 0.f);
        }
        for (int it = 0; it < 5; it++) {
            #pragma unroll
            for (int i = 0; i < 4; i++) {
                float s = Mm[i*4+0] + Mm[i*4+1] + Mm[i*4+2] + Mm[i*4+3] + 1e-6f;
                float inv = 1.f / s;
                #pragma unroll
                for (int j = 0; j < 4; j++) Mm[i*4+j] *= inv;
            }
            #pragma unroll
            for (int j = 0; j < 4; j++) {
                float s = Mm[0*4+j] + Mm[1*4+j] + Mm[2*4+j] + Mm[3*4+j] + 1e-6f;
                float inv = 1.f / s;
                #pragma unroll
                for (int i = 0; i < 4; i++) Mm[i*4+j] *= inv;
            }
        }
        #pragma unroll
        for (int i = 0; i < 16; i++) sM[i] = Mm[i];
    }
    float ss = v.x*v.x + v.y*v.y + v.z*v.z + v.w*v.w;
    #pragma unroll
    for (int o = 16; o > 0; o >>= 1) ss += __shfl_xor_sync(0xffffffffu, ss, o);
    if ((tid & 31) == 0) red[tid >> 5] = ss;
    __syncthreads();
    if (tid == 0) {
        float tot = 0.f;
        #pragma unroll
        for (int i = 0; i < 8; i++) tot += red[i];
        s_scale = rsqrtf(tot * (1.0f / DMODEL) + EPS_RMS);
    }
    __syncthreads();
    float sc = s_scale;
    float4 wv = ((const float4*)w)[tid];
    float o0 = v.x*sc*wv.x, o1 = v.y*sc*wv.y, o2 = v.z*sc*wv.z, o3 = v.w*sc*wv.w;
    __nv_bfloat16 h0 = __float2bfloat16(o0), h1 = __float2bfloat16(o1);
    __nv_bfloat16 h2 = __float2bfloat16(o2), h3 = __float2bfloat16(o3);
    __nv_bfloat16 l0 = __float2bfloat16(o0 - __bfloat162float(h0));
    __nv_bfloat16 l1 = __float2bfloat16(o1 - __bfloat162float(h1));
    __nv_bfloat16 l2 = __float2bfloat16(o2 - __bfloat162float(h2));
    __nv_bfloat16 l3 = __float2bfloat16(o3 - __bfloat162float(h3));
    __nv_bfloat162* dh = (__nv_bfloat162*)(hi + (size_t)row * DMODEL);
    __nv_bfloat162* dl = (__nv_bfloat162*)(lo + (size_t)row * DMODEL);
    dh[tid*2]   = __halves2bfloat162(h0, h1);
    dh[tid*2+1] = __halves2bfloat162(h2, h3);
    dl[tid*2]   = __halves2bfloat162(l0, l1);
    dl[tid*2+1] = __halves2bfloat162(l2, l3);
    float hh0 = sr[tid], hh1 = sr[256 + tid], hh2 = sr[512 + tid], hh3 = sr[768 + tid];
    float* o = g_Hres + (size_t)row * DMODEL;
    #pragma unroll
    for (int j = 0; j < 4; j++)
        o[j*256 + tid] = sM[j*4+0]*hh0 + sM[j*4+1]*hh1 + sM[j*4+2]*hh2 + sM[j*4+3]*hh3;
}

// ---------------- RMS norm, fp16 output (head path) ----------------
__global__ void k_rms_f16(const float* __restrict__ w,
                          const float* __restrict__ src,
                          __half* __restrict__ dst) {
    int row = blockIdx.x, tid = threadIdx.x;
    float4 v = ((const float4*)(src + (size_t)row * DMODEL))[tid];
    float ss = v.x*v.x + v.y*v.y + v.z*v.z + v.w*v.w;
    #pragma unroll
    for (int o = 16; o > 0; o >>= 1) ss += __shfl_xor_sync(0xffffffffu, ss, o);
    __shared__ float red[8];
    __shared__ float s_scale;
    if ((tid & 31) == 0) red[tid >> 5] = ss;
    __syncthreads();
    if (tid == 0) {
        float tot = 0.f;
        #pragma unroll
        for (int i = 0; i < 8; i++) tot += red[i];
        s_scale = rsqrtf(tot * (1.0f / DMODEL) + EPS_RMS);
    }
    __syncthreads();
    float sc = s_scale;
    float4 wv = ((const float4*)w)[tid];
    __half2* dh = (__half2*)(dst + (size_t)row * DMODEL);
    dh[tid*2]   = __floats2half2_rn(v.x*sc*wv.x, v.y*sc*wv.y);
    dh[tid*2+1] = __floats2half2_rn(v.z*sc*wv.z, v.w*sc*wv.w);
}

// ---------------- scan phase 1: per-chunk local scan (dt/dtA inline) ----------------
__global__ void __launch_bounds__(64) k_scan1(const float* __restrict__ dt_bias,
                                              const float* __restrict__ A_log, int l) {
    int pblk = blockIdx.x, h = blockIdx.y;
    int b = blockIdx.z >> 5, c = blockIdx.z & 31;
    int tid = threadIdx.x;
    int p = pblk * 64 + tid;
    int t0 = c * TCH;
    float dtb = dt_bias[l*NHEADS + h];
    float Ah  = -expf(A_log[l*NHEADS + h]);
    __shared__ float sBC[2][128];
    float hs[64];
    #pragma unroll
    for (int n = 0; n < 64; n++) hs[n] = 0.f;
    float P = 1.f;

    float nb0, nb1, nx, ndt, ndA;
    {
        size_t r0 = (size_t)(b * L_SEQ + t0) * DPROJ;
        nb0 = g_zx[r0 + 2*DIN + NHEADS + h*128 + tid];
        nb1 = g_zx[r0 + 2*DIN + NHEADS + h*128 + 64 + tid];
        nx  = g_zx[r0 + DIN + h*PDIM + p];
        float v = g_zx[r0 + 2*DIN + h] + dtb;
        ndt = fmaxf(v, 0.f) + log1pf(expf(-fabsf(v)));
        ndA = expf(ndt * Ah);
    }
    sBC[0][tid] = nb0; sBC[0][64 + tid] = nb1;
    __syncthreads();

    for (int i = 0; i < TCH; i++) {
        int t = t0 + i;
        int buf = i & 1;
        float cx = nx, cdt = ndt, cdA = ndA;
        if (i + 1 < TCH) {
            size_t r1 = (size_t)(b * L_SEQ + t + 1) * DPROJ;
            nb0 = g_zx[r1 + 2*DIN + NHEADS + h*128 + tid];
            nb1 = g_zx[r1 + 2*DIN + NHEADS + h*128 + 64 + tid];
            nx  = g_zx[r1 + DIN + h*PDIM + p];
            float v = g_zx[r1 + 2*DIN + h] + dtb;
            ndt = fmaxf(v, 0.f) + log1pf(expf(-fabsf(v)));
            ndA = expf(ndt * Ah);
        }
        float ux = cdt * cx;
        float y0 = 0.f, y1 = 0.f, y2a = 0.f, y3 = 0.f;
        #pragma unroll
        for (int n4 = 0; n4 < 16; n4++) {
            float4 Bq = *(const float4*)&sBC[buf][n4 * 4];
            float4 Cq = *(const float4*)&sBC[buf][64 + n4 * 4];
            hs[n4*4+0] = fmaf(hs[n4*4+0], cdA, Bq.x * ux);
            hs[n4*4+1] = fmaf(hs[n4*4+1], cdA, Bq.y * ux);
            hs[n4*4+2] = fmaf(hs[n4*4+2], cdA, Bq.z * ux);
            hs[n4*4+3] = fmaf(hs[n4*4+3], cdA, Bq.w * ux);
            y0  = fmaf(Cq.x, hs[n4*4+0], y0);
            y1  = fmaf(Cq.y, hs[n4*4+1], y1);
            y2a = fmaf(Cq.z, hs[n4*4+2], y2a);
            y3  = fmaf(Cq.w, hs[n4*4+3], y3);
        }
        P *= cdA;
        if (pblk == 0 && tid == 0)
            g_cumA[(b * L_SEQ + t) * NHEADS + h] = P;
        g_ylocal[(size_t)(b * L_SEQ + t) * DIN + h * PDIM + p] =
            (y0 + y1) + (y2a + y3);
        sBC[buf ^ 1][tid] = nb0;
        sBC[buf ^ 1][64 + tid] = nb1;
        __syncthreads();
    }
    size_t sb = ((size_t)((b * NHEADS + h) * NCHUNK + c)) * DSTATE * PDIM;
    #pragma unroll
    for (int n = 0; n < 64; n++)
        g_S[sb + n * PDIM + p] = hs[n];
}

// ---------------- scan phase 2: inter-chunk recurrence (in place) ----------------
__global__ void k_scan2() {
    int bh = blockIdx.x;
    int b = bh >> 2, h = bh & 3;
    int idx = blockIdx.y * 256 + threadIdx.x;
    int n = idx >> 9, p = idx & 511;
    size_t base = ((size_t)bh * NCHUNK) * DSTATE * PDIM + n * PDIM + p;
    float prev = 0.f;
    for (int c = 0; c < NCHUNK; c++) {
        float Q = g_cumA[(b * L_SEQ + c * TCH + TCH - 1) * NHEADS + h];
        size_t o = base + (size_t)c * DSTATE * PDIM;
        float s = g_S[o];
        g_S[o] = prev;
        prev = fmaf(Q, prev, s);
    }
}

// ---------------- scan phase 3: correction + epilogue + bf16 split ----------------
__global__ void __launch_bounds__(256) k_scan3(const float* __restrict__ Dp, int l) {
    int c = blockIdx.x, h = blockIdx.y, b = blockIdx.z;
    int tid = threadIdx.x;
    __shared__ float sC[64][65];
    __shared__ float sP[64];
    __shared__ float shin[64][128];
    #pragma unroll
    for (int i = 0; i < 16; i++) {
        int e = tid + i * 256;
        int t = e >> 6, n = e & 63;
        int row = b * L_SEQ + c * TCH + t;
        sC[t][n] = g_zx[(size_t)row * DPROJ + 2*DIN + NHEADS + h*128 + 64 + n];
    }
    if (tid < 64)
        sP[tid] = g_cumA[(b * L_SEQ + c * TCH + tid) * NHEADS + h];
    float Dh = Dp[l * NHEADS + h];
    __syncthreads();

    size_t hb = ((size_t)((b * NHEADS + h) * NCHUNK + c)) * DSTATE * PDIM;
    int pl = tid & 127, tb = (tid >> 7) * 32;
    #pragma unroll
    for (int pt = 0; pt < 4; pt++) {
        int p0 = pt * 128;
        #pragma unroll
        for (int i = 0; i < 32; i++) {
            int e = tid + i * 256;
            int n = e >> 7, pp = e & 127;
            shin[n][pp] = g_S[hb + n * PDIM + p0 + pp];
        }
        __syncthreads();
        int p = p0 + pl;
        for (int tt = 0; tt < 32; tt++) {
            int t = tb + tt;
            float a0 = 0.f, a1 = 0.f;
            #pragma unroll
            for (int n = 0; n < 64; n += 2) {
                a0 = fmaf(sC[t][n],   shin[n][pl],   a0);
                a1 = fmaf(sC[t][n+1], shin[n+1][pl], a1);
            }
            int row = b * L_SEQ + c * TCH + t;
            size_t zo = (size_t)row * DPROJ;
            float x = g_zx[zo + DIN + h*PDIM + p];
            float z = g_zx[zo + h*PDIM + p];
            float yl = g_ylocal[(size_t)row * DIN + h*PDIM + p];
            float y = yl + sP[t] * (a0 + a1) + x * Dh;
            float sig = 1.f / (1.f + expf(-z));
            float out = y * (z * sig);
            size_t oi = (size_t)row * DIN + h * PDIM + p;
            __nv_bfloat16 oh = __float2bfloat16(out);
            g_Ahi[oi] = oh;
            g_Alo[oi] = __float2bfloat16(out - __bfloat162float(oh));
        }
        __syncthreads();
    }
}

// ================= shared GEMM helpers =================
#define KT      32
#define ASTRIDE (KT + 8)               /* 40 elems */
#define STAGE_A (128 * ASTRIDE)        /* 5120 elems */
#define GBN     128
#define GBSTR   (GBN + 8)              /* 136 */
#define GSTB    (KT * GBSTR)           /* 4352 elems */

__device__ __forceinline__ uint32_t smem_u32(const void* p) {
    return (uint32_t)__cvta_generic_to_shared(p);
}
__device__ __forceinline__ void cp16(uint32_t dst, const void* src) {
    asm volatile("cp.async.cg.shared.global [%0],[%1],16;\n" :: "r"(dst), "l"(src));
}
__device__ __forceinline__ void cp16z(uint32_t dst, const void* src, int bytes) {
    asm volatile("cp.async.cg.shared.global [%0],[%1],16,%2;\n" :: "r"(dst), "l"(src), "r"(bytes));
}
template<int G>
__device__ __forceinline__ void wgroup() {
    asm volatile("cp.async.wait_group %0;\n" :: "n"(G));
}
__device__ __forceinline__ void ldsm_x4(uint32_t* r, uint32_t a) {
    asm volatile("ldmatrix.sync.aligned.m8n8.x4.shared.b16 {%0,%1,%2,%3}, [%4];\n"
        : "=r"(r[0]), "=r"(r[1]), "=r"(r[2]), "=r"(r[3]) : "r"(a));
}
__device__ __forceinline__ void ldsm_x4t(uint32_t* r, uint32_t a) {
    asm volatile("ldmatrix.sync.aligned.m8n8.x4.trans.shared.b16 {%0,%1,%2,%3}, [%4];\n"
        : "=r"(r[0]), "=r"(r[1]), "=r"(r[2]), "=r"(r[3]) : "r"(a));
}
__device__ __forceinline__ void mma_bf16(float* c, const uint32_t* a, const uint32_t* b) {
    asm volatile(
        "mma.sync.aligned.m16n8k16.row.col.f32.bf16.bf16.f32 "
        "{%0,%1,%2,%3}, {%4,%5,%6,%7}, {%8,%9}, {%0,%1,%2,%3};\n"
        : "+f"(c[0]), "+f"(c[1]), "+f"(c[2]), "+f"(c[3])
        : "r"(a[0]), "r"(a[1]), "r"(a[2]), "r"(a[3]), "r"(b[0]), "r"(b[1]));
}
__device__ __forceinline__ void mma_f16(float* c, const uint32_t* a, const uint32_t* b) {
    asm volatile(
        "mma.sync.aligned.m16n8k16.row.col.f32.f16.f16.f32 "
        "{%0,%1,%2,%3}, {%4,%5,%6,%7}, {%8,%9}, {%0,%1,%2,%3};\n"
        : "+f"(c[0]), "+f"(c[1]), "+f"(c[2]), "+f"(c[3])
        : "r"(a[0]), "r"(a[1]), "r"(a[2]), "r"(a[3]), "r"(b[0]), "r"(b[1]));
}

// ================= bf16x3 GEMM (layers): 128x128 tile, 3 stages, 2 CTAs/SM =================
#define GSTAGES 3
#define GSELEMS (2*STAGE_A + 2*GSTB)           /* 18944 elems */
#define GSMEM   (GSTAGES * GSELEMS * 2)        /* 113664 B */

template<bool NGUARD>
__device__ __forceinline__ void load_stage(
    __nv_bfloat16* sb,
    const __nv_bfloat16* __restrict__ Ahi, const __nv_bfloat16* __restrict__ Alo,
    const __nv_bfloat16* __restrict__ Bhi, const __nv_bfloat16* __restrict__ Blo,
    int row0, int col0, int k0, int N, int Nld, int K, int tid)
{
    #pragma unroll
    for (int i = 0; i < 2; i++) {
        int c  = tid * 2 + i;
        int r  = c >> 2;
        int kc = (c & 3) * 8;
        size_t go = (size_t)(row0 + r) * K + k0 + kc;
        cp16(smem_u32(sb + r * ASTRIDE + kc),            Ahi + go);
        cp16(smem_u32(sb + STAGE_A + r * ASTRIDE + kc),  Alo + go);
    }
    #pragma unroll
    for (int i = 0; i < 2; i++) {
        int c   = tid + i * 256;
        int r   = c >> 4;
        int nc  = (c & 15) * 8;
        int col = col0 + nc;
        size_t go = (size_t)(k0 + r) * Nld + col;
        uint32_t dH = smem_u32(sb + 2*STAGE_A + r * GBSTR + nc);
        uint32_t dL = smem_u32(sb + 2*STAGE_A + GSTB + r * GBSTR + nc);
        if (!NGUARD) {
            cp16(dH, Bhi + go);
            cp16(dL, Blo + go);
        } else {
            int rem = N - col;
            if (rem >= 8) {
                cp16(dH, Bhi + go);
                cp16(dL, Blo + go);
            } else if (rem > 0) {
                cp16z(dH, Bhi + go, rem * 2);
                cp16z(dL, Blo + go, rem * 2);
            } else {
                uint4 z = make_uint4(0, 0, 0, 0);
                *(uint4*)(sb + 2*STAGE_A + r * GBSTR + nc) = z;
                *(uint4*)(sb + 2*STAGE_A + GSTB + r * GBSTR + nc) = z;
            }
        }
    }
}

template <bool RES>
__global__ void __launch_bounds__(256, 2) k_gemm3(
    const __nv_bfloat16* __restrict__ Ahi, const __nv_bfloat16* __restrict__ Alo,
    const __nv_bfloat16* __restrict__ Bhi, const __nv_bfloat16* __restrict__ Blo,
    const float* __restrict__ bias, const float* __restrict__ Rs,
    float* __restrict__ C, int M, int N, int Nld, int K)
{
    extern __shared__ __nv_bfloat16 smem[];
    int tid  = threadIdx.x;
    int row0 = blockIdx.x * 128, col0 = blockIdx.y * GBN;
    bool nguard = (col0 + GBN > N);
    int ktiles = K / KT;

    #pragma unroll
    for (int s = 0; s < GSTAGES - 1; s++) {
        __nv_bfloat16* sb = smem + s * GSELEMS;
        if (nguard) load_stage<true >(sb, Ahi, Alo, Bhi, Blo, row0, col0, s*KT, N, Nld, K, tid);
        else        load_stage<false>(sb, Ahi, Alo, Bhi, Blo, row0, col0, s*KT, N, Nld, K, tid);
        asm volatile("cp.async.commit_group;\n");
    }

    int lane = tid & 31, wid = tid >> 5;
    int wm = (wid & 1) * 64, wn = (wid >> 1) * 32;
    int a_r = lane & 15, a_c = (lane >> 4) * 8;
    int l8 = lane & 7, mat = lane >> 3;
    int brow = (mat & 1) * 8 + l8;
    int bcol = (mat >> 1) * 8;

    float acc[4][4][4];
    #pragma unroll
    for (int mt = 0; mt < 4; mt++)
        #pragma unroll
        for (int nt = 0; nt < 4; nt++)
            #pragma unroll
            for (int q = 0; q < 4; q++) acc[mt][nt][q] = 0.f;

    for (int kt = 0; kt < ktiles; kt++) {
        int rem = ktiles - 1 - kt;
        if (rem >= 1) wgroup<1>();
        else          wgroup<0>();
        __syncthreads();
        if (kt + GSTAGES - 1 < ktiles) {
            __nv_bfloat16* sb = smem + ((kt + GSTAGES - 1) % GSTAGES) * GSELEMS;
            int k0 = (kt + GSTAGES - 1) * KT;
            if (nguard) load_stage<true >(sb, Ahi, Alo, Bhi, Blo, row0, col0, k0, N, Nld, K, tid);
            else        load_stage<false>(sb, Ahi, Alo, Bhi, Blo, row0, col0, k0, N, Nld, K, tid);
            asm volatile("cp.async.commit_group;\n");
        }
        __nv_bfloat16* sb = smem + (kt % GSTAGES) * GSELEMS;
        __nv_bfloat16* sbB = sb + 2*STAGE_A;
        #pragma unroll
        for (int ks = 0; ks < 2; ks++) {
            uint32_t afh[4][4], afl[4][4];
            #pragma unroll
            for (int mt = 0; mt < 4; mt++) {
                int r = wm + mt*16 + a_r;
                ldsm_x4(afh[mt], smem_u32(sb + r*ASTRIDE + ks*16 + a_c));
                ldsm_x4(afl[mt], smem_u32(sb + STAGE_A + r*ASTRIDE + ks*16 + a_c));
            }
            #pragma unroll
            for (int np = 0; np < 2; np++) {
                uint32_t bh[4], bl[4];
                int boff = (ks*16 + brow)*GBSTR + wn + np*16 + bcol;
                ldsm_x4t(bh, smem_u32(sbB + boff));
                ldsm_x4t(bl, smem_u32(sbB + GSTB + boff));
                #pragma unroll
                for (int mt = 0; mt < 4; mt++) {
                    mma_bf16(acc[mt][np*2],   afh[mt], bh);
                    mma_bf16(acc[mt][np*2],   afh[mt], bl);
                    mma_bf16(acc[mt][np*2],   afl[mt], bh);
                    mma_bf16(acc[mt][np*2+1], afh[mt], bh + 2);
                    mma_bf16(acc[mt][np*2+1], afh[mt], bl + 2);
                    mma_bf16(acc[mt][np*2+1], afl[mt], bh + 2);
                }
            }
        }
    }

    #pragma unroll
    for (int mt = 0; mt < 4; mt++) {
        int r0 = row0 + wm + mt*16 + (lane >> 2);
        int r1 = r0 + 8;
        #pragma unroll
        for (int nt = 0; nt < 4; nt++) {
            int c0 = col0 + wn + nt*8 + (lane & 3)*2;
            float* a = acc[mt][nt];
            if (c0 < N) {
                float v0 = a[0] + bias[c0];
                float v2 = a[2] + bias[c0];
                if (RES) { v0 += Rs[(size_t)r0*N + c0]; v2 += Rs[(size_t)r1*N + c0]; }
                C[(size_t)r0*N + c0] = v0;
                C[(size_t)r1*N + c0] = v2;
            }
            if (c0 + 1 < N) {
                float v1 = a[1] + bias[c0+1];
                float v3 = a[3] + bias[c0+1];
                if (RES) { v1 += Rs[(size_t)r0*N + c0+1]; v3 += Rs[(size_t)r1*N + c0+1]; }
                C[(size_t)r0*N + c0+1] = v1;
                C[(size_t)r1*N + c0+1] = v3;
            }
        }
    }
}

// ================= fp16x1 GEMM (head): 128x128 tile, KT=64, 3 stages, 2 CTAs/SM =================
#define HKT     64
#define HASTR   (HKT + 8)              /* 72 elems */
#define HSTGA   (128 * HASTR)          /* 9216 elems */
#define HSTB    (HKT * GBSTR)          /* 8704 elems */
#define HSELEMS (HSTGA + HSTB)         /* 17920 elems = 35840 B */
#define HSTAGES 3
#define HSMEM   (HSTAGES * HSELEMS * 2) /* 107520 B */

__device__ __forceinline__ void load_stage_h(
    __half* sb,
    const __half* __restrict__ A, const __half* __restrict__ B,
    int row0, int col0, int k0, int N, int K, int tid)
{
    // A: 128 rows x 64 k = 1024 chunks of 8, 4/thread
    #pragma unroll
    for (int i = 0; i < 4; i++) {
        int c  = tid + i * 256;
        int r  = c >> 3;
        int kc = (c & 7) * 8;
        cp16(smem_u32(sb + r * HASTR + kc), A + (size_t)(row0 + r) * K + k0 + kc);
    }
    // B: 64 k-rows x 128 n = 1024 chunks of 8, 4/thread
    #pragma unroll
    for (int i = 0; i < 4; i++) {
        int c   = tid + i * 256;
        int r   = c >> 4;
        int nc  = (c & 15) * 8;
        size_t go = (size_t)(k0 + r) * N + col0 + nc;
        cp16(smem_u32(sb + HSTGA + r * GBSTR + nc), B + go);
    }
}

__global__ void __launch_bounds__(256, 2) k_gemm1h(
    const __half* __restrict__ A, const __half* __restrict__ B,
    const float* __restrict__ bias,
    float* __restrict__ C, int M, int N, int K)
{
    extern __shared__ __half hsmem[];
    int tid  = threadIdx.x;
    int row0 = blockIdx.x * 128, col0 = blockIdx.y * GBN;
    int ktiles = K / HKT;   /* 16 */

    #pragma unroll
    for (int s = 0; s < HSTAGES - 1; s++) {
        load_stage_h(hsmem + s * HSELEMS, A, B, row0, col0, s*HKT, N, K, tid);
        asm volatile("cp.async.commit_group;\n");
    }

    int lane = tid & 31, wid = tid >> 5;
    int wm = (wid & 1) * 64, wn = (wid >> 1) * 32;
    int a_r = lane & 15, a_c = (lane >> 4) * 8;
    int l8 = lane & 7, mat = lane >> 3;
    int brow = (mat & 1) * 8 + l8;
    int bcol = (mat >> 1) * 8;

    float acc[4][4][4];
    #pragma unroll
    for (int mt = 0; mt < 4; mt++)
        #pragma unroll
        for (int nt = 0; nt < 4; nt++)
            #pragma unroll
            for (int q = 0; q < 4; q++) acc[mt][nt][q] = 0.f;

    for (int kt = 0; kt < ktiles; kt++) {
        int rem = ktiles - 1 - kt;
        if (rem >= 1) wgroup<1>();
        else          wgroup<0>();
        __syncthreads();
        if (kt + HSTAGES - 1 < ktiles) {
            load_stage_h(hsmem + ((kt + HSTAGES - 1) % HSTAGES) * HSELEMS,
                         A, B, row0, col0, (kt + HSTAGES - 1) * HKT, N, K, tid);
            asm volatile("cp.async.commit_group;\n");
        }
        __half* sb  = hsmem + (kt % HSTAGES) * HSELEMS;
        __half* sbB = sb + HSTGA;
        #pragma unroll
        for (int ks = 0; ks < 4; ks++) {
            uint32_t af[4][4];
            #pragma unroll
            for (int mt = 0; mt < 4; mt++) {
                int r = wm + mt*16 + a_r;
                ldsm_x4(af[mt], smem_u32(sb + r*HASTR + ks*16 + a_c));
            }
            #pragma unroll
            for (int np = 0; np < 2; np++) {
                uint32_t bb[4];
                int boff = (ks*16 + brow)*GBSTR + wn + np*16 + bcol;
                ldsm_x4t(bb, smem_u32(sbB + boff));
                #pragma unroll
                for (int mt = 0; mt < 4; mt++) {
                    mma_f16(acc[mt][np*2],   af[mt], bb);
                    mma_f16(acc[mt][np*2+1], af[mt], bb + 2);
                }
            }
        }
    }

    #pragma unroll
    for (int mt = 0; mt < 4; mt++) {
        int r0 = row0 + wm + mt*16 + (lane >> 2);
        int r1 = r0 + 8;
        #pragma unroll
        for (int nt = 0; nt < 4; nt++) {
            int c0 = col0 + wn + nt*8 + (lane & 3)*2;
            float* a = acc[mt][nt];
            float b0 = bias[c0], b1 = bias[c0+1];
            C[(size_t)r0*N + c0]     = a[0] + b0;
            C[(size_t)r0*N + c0 + 1] = a[1] + b1;
            C[(size_t)r1*N + c0]     = a[2] + b0;
            C[(size_t)r1*N + c0 + 1] = a[3] + b1;
        }
    }
}

// ---------------- host orchestration ----------------
extern "C" void kernel_launch(void* const* d_in, const int* in_sizes, int n_in,
                              void* d_out, int out_size) {
    const int*   tokens  = (const int*)  d_in[0];
    const float* embed   = (const float*)d_in[1];
    const float* norm_w  = (const float*)d_in[2];
    const float* Wi      = (const float*)d_in[3];
    const float* bi      = (const float*)d_in[4];
    const float* A_log   = (const float*)d_in[5];
    const float* Dp      = (const float*)d_in[6];
    const float* dt_bias = (const float*)d_in[7];
    const float* Wo      = (const float*)d_in[8];
    const float* bo      = (const float*)d_in[9];
    const float* mixl    = (const float*)d_in[10];
    const float* norm_f  = (const float*)d_in[11];
    const float* headW   = (const float*)d_in[12];
    const float* headb   = (const float*)d_in[13];
    float* out = (float*)d_out;

    cudaFuncSetAttribute((const void*)k_gemm3<false>, cudaFuncAttributeMaxDynamicSharedMemorySize, GSMEM);
    cudaFuncSetAttribute((const void*)k_gemm3<true >, cudaFuncAttributeMaxDynamicSharedMemorySize, GSMEM);
    cudaFuncSetAttribute((const void*)k_gemm1h,       cudaFuncAttributeMaxDynamicSharedMemorySize, HSMEM);

    void *pH, *pHres, *pzx, *pAhi, *pAlo, *pWiHi, *pWiLo, *pWoHi, *pWoLo, *pHB;
    cudaGetSymbolAddress(&pH,    g_H);
    cudaGetSymbolAddress(&pHres, g_Hres);
    cudaGetSymbolAddress(&pzx,   g_zx);
    cudaGetSymbolAddress(&pAhi,  g_Ahi);
    cudaGetSymbolAddress(&pAlo,  g_Alo);
    cudaGetSymbolAddress(&pWiHi, g_WiHi);
    cudaGetSymbolAddress(&pWiLo, g_WiLo);
    cudaGetSymbolAddress(&pWoHi, g_WoHi);
    cudaGetSymbolAddress(&pWoLo, g_WoLo);
    cudaGetSymbolAddress(&pHB,   g_HB);
    float* fH    = (float*)pH;
    float* fHres = (float*)pHres;
    float* fzx   = (float*)pzx;
    __nv_bfloat16* Ahi  = (__nv_bfloat16*)pAhi;
    __nv_bfloat16* Alo  = (__nv_bfloat16*)pAlo;
    __nv_bfloat16* WiHi = (__nv_bfloat16*)pWiHi;
    __nv_bfloat16* WiLo = (__nv_bfloat16*)pWiLo;
    __nv_bfloat16* WoHi = (__nv_bfloat16*)pWoHi;
    __nv_bfloat16* WoLo = (__nv_bfloat16*)pWoLo;
    __half* hB = (__half*)pHB;
    __half* hA = (__half*)pAhi;   // head A reuses g_Ahi storage as fp16

    k_embed<<<NROWS, 256>>>(tokens, embed);
    k_splitAll<<<WI_BLKS + WO_BLKS + HD_BLKS, 256>>>(Wi, Wo, headW);

    for (int l = 0; l < NLAYERS; l++) {
        k_pre<<<NROWS, 256>>>(mixl + l * 16, norm_w + (size_t)l * DMODEL, Ahi, Alo);
        k_gemm3<false><<<dim3(NROWS / 128, (DPROJ + GBN - 1) / GBN), 256, GSMEM>>>(
            Ahi, Alo,
            WiHi + (size_t)l * DMODEL * NPAD_I, WiLo + (size_t)l * DMODEL * NPAD_I,
            bi + (size_t)l * DPROJ, nullptr,
            fzx, NROWS, DPROJ, NPAD_I, DMODEL);
        k_scan1<<<dim3(8, NHEADS, BATCH * NCHUNK), 64>>>(dt_bias, A_log, l);
        k_scan2<<<dim3(BATCH * NHEADS, 128), 256>>>();
        k_scan3<<<dim3(NCHUNK, NHEADS, BATCH), 256>>>(Dp, l);
        k_gemm3<true><<<dim3(NROWS / 128, DMODEL / GBN), 256, GSMEM>>>(
            Ahi, Alo,
            WoHi + (size_t)l * DIN * DMODEL, WoLo + (size_t)l * DIN * DMODEL,
            bo + (size_t)l * DMODEL, fHres,
            fH, NROWS, DMODEL, DMODEL, DIN);
    }

    // head: plain fp16, KT=64, 3 stages
    k_rms_f16<<<NROWS, 256>>>(norm_f, fH, hA);
    k_gemm1h<<<dim3(NROWS / 128, VOCAB / GBN), 256, HSMEM>>>(
        hA, hB, headb, out, NROWS, VOCAB, DMODEL);
}

// round 16
// speedup vs baseline: 1.1412x; 1.0025x over previous
#include <cuda_runtime.h>
#include <cuda_bf16.h>
#include <cuda_fp16.h>
#include <math.h>
#include <stdint.h>

#define L_SEQ   2048
#define BATCH   2
#define DMODEL  1024
#define DIN     2048
#define NHEADS  4
#define PDIM    512
#define DSTATE  64
#define DPROJ   4612
#define NPAD_I  4616
#define NROWS   4096   /* BATCH * L_SEQ */
#define VOCAB   32000
#define NLAYERS 4
#define NCHUNK  32
#define TCH     64
#define EPS_RMS 1.1920929e-07f

// ---------------- scratch (__device__ globals: alloc-free) ----------------
__device__ float g_H   [NROWS * DMODEL];
__device__ float g_Hres[NROWS * DMODEL];
__device__ float g_zx  [NROWS * DPROJ];
__device__ float g_cumA[NROWS * NHEADS];
__device__ float g_ylocal[NROWS * DIN];
__device__ float g_S[BATCH * NHEADS * NCHUNK * DSTATE * PDIM];
__device__ __align__(16) __nv_bfloat16 g_Ahi[NROWS * DIN];
__device__ __align__(16) __nv_bfloat16 g_Alo[NROWS * DIN];
__device__ __align__(16) __nv_bfloat16 g_WiHi[NLAYERS * DMODEL * NPAD_I];
__device__ __align__(16) __nv_bfloat16 g_WiLo[NLAYERS * DMODEL * NPAD_I];
__device__ __align__(16) __nv_bfloat16 g_WoHi[NLAYERS * DIN * DMODEL];
__device__ __align__(16) __nv_bfloat16 g_WoLo[NLAYERS * DIN * DMODEL];
__device__ __align__(16) __half g_HB[DMODEL * VOCAB];

// ---------------- embedding gather ----------------
__global__ void k_embed(const int* __restrict__ tokens,
                        const float* __restrict__ embed) {
    int row = blockIdx.x;
    int t   = threadIdx.x;
    int tok = tokens[row];
    const float4* src = (const float4*)(embed + (size_t)tok * DMODEL);
    ((float4*)(g_H + (size_t)row * DMODEL))[t] = src[t];
}

// ---------------- all weight splits, one launch ----------------
#define WI_BLKS (NLAYERS * DMODEL * 5)   /* 20480 */
#define WO_BLKS (NLAYERS * DIN)          /* 8192  */
#define HD_BLKS (32 * DMODEL)            /* 32768 */
__global__ void __launch_bounds__(256) k_splitAll(
    const float* __restrict__ Wi, const float* __restrict__ Wo,
    const float* __restrict__ headW)
{
    int id = blockIdx.x, tid = threadIdx.x;
    if (id < WI_BLKS) {
        int l = id / (DMODEL * 5);
        int rem = id % (DMODEL * 5);
        int r = rem / 5, sub = rem % 5;
        int c4 = (sub * 256 + tid) * 4;
        if (c4 >= DPROJ) return;
        float4 v = *(const float4*)(Wi + (size_t)l * DMODEL * DPROJ + (size_t)r * DPROJ + c4);
        __nv_bfloat16 h0 = __float2bfloat16(v.x), h1 = __float2bfloat16(v.y);
        __nv_bfloat16 h2 = __float2bfloat16(v.z), h3 = __float2bfloat16(v.w);
        __nv_bfloat16 l0 = __float2bfloat16(v.x - __bfloat162float(h0));
        __nv_bfloat16 l1 = __float2bfloat16(v.y - __bfloat162float(h1));
        __nv_bfloat16 l2 = __float2bfloat16(v.z - __bfloat162float(h2));
        __nv_bfloat16 l3 = __float2bfloat16(v.w - __bfloat162float(h3));
        size_t o = (size_t)l * DMODEL * NPAD_I + (size_t)r * NPAD_I + c4;
        *(__nv_bfloat162*)(g_WiHi + o)     = __halves2bfloat162(h0, h1);
        *(__nv_bfloat162*)(g_WiHi + o + 2) = __halves2bfloat162(h2, h3);
        *(__nv_bfloat162*)(g_WiLo + o)     = __halves2bfloat162(l0, l1);
        *(__nv_bfloat162*)(g_WiLo + o + 2) = __halves2bfloat162(l2, l3);
    } else if (id < WI_BLKS + WO_BLKS) {
        int id2 = id - WI_BLKS;
        int l = id2 / DIN, r = id2 % DIN;
        int c4 = tid * 4;
        float4 v = *(const float4*)(Wo + (size_t)l * DIN * DMODEL + (size_t)r * DMODEL + c4);
        __nv_bfloat16 h0 = __float2bfloat16(v.x), h1 = __float2bfloat16(v.y);
        __nv_bfloat16 h2 = __float2bfloat16(v.z), h3 = __float2bfloat16(v.w);
        __nv_bfloat16 l0 = __float2bfloat16(v.x - __bfloat162float(h0));
        __nv_bfloat16 l1 = __float2bfloat16(v.y - __bfloat162float(h1));
        __nv_bfloat16 l2 = __float2bfloat16(v.z - __bfloat162float(h2));
        __nv_bfloat16 l3 = __float2bfloat16(v.w - __bfloat162float(h3));
        size_t o = (size_t)l * DIN * DMODEL + (size_t)r * DMODEL + c4;
        *(__nv_bfloat162*)(g_WoHi + o)     = __halves2bfloat162(h0, h1);
        *(__nv_bfloat162*)(g_WoHi + o + 2) = __halves2bfloat162(h2, h3);
        *(__nv_bfloat162*)(g_WoLo + o)     = __halves2bfloat162(l0, l1);
        *(__nv_bfloat162*)(g_WoLo + o + 2) = __halves2bfloat162(l2, l3);
    } else {
        int id3 = id - WI_BLKS - WO_BLKS;
        int r = id3 >> 5, sub = id3 & 31;
        int c4 = (sub * 256 + tid) * 4;
        if (c4 >= VOCAB) return;
        float4 v = *(const float4*)(headW + (size_t)r * VOCAB + c4);
        size_t o = (size_t)r * VOCAB + c4;
        *(__half2*)(g_HB + o)     = __floats2half2_rn(v.x, v.y);
        *(__half2*)(g_HB + o + 2) = __floats2half2_rn(v.z, v.w);
    }
}

// ---------------- fused layer prep: sinkhorn + hres + rms + bf16 split ----------------
__global__ void __launch_bounds__(256) k_pre(const float* __restrict__ logits,
                                             const float* __restrict__ w,
                                             __nv_bfloat16* __restrict__ hi,
                                             __nv_bfloat16* __restrict__ lo) {
    __shared__ float sr[1024];
    __shared__ float sM[16];
    __shared__ float red[8];
    __shared__ float s_scale;
    int row = blockIdx.x, tid = threadIdx.x;
    float4 v = ((const float4*)(g_H + (size_t)row * DMODEL))[tid];
    *(float4*)&sr[tid * 4] = v;
    if (tid == 0) {
        float Mm[16];
        #pragma unroll
        for (int i = 0; i < 16; i++) {
            float s = 1.f / (1.f + expf(-logits[i]));
            Mm[i] = s + (((i >> 2) == (i & 3)) ? 1.f : 0.f);
        }
        for (int it = 0; it < 5; it++) {
            #pragma unroll
            for (int i = 0; i < 4; i++) {
                float s = Mm[i*4+0] + Mm[i*4+1] + Mm[i*4+2] + Mm[i*4+3] + 1e-6f;
                float inv = 1.f / s;
                #pragma unroll
                for (int j = 0; j < 4; j++) Mm[i*4+j] *= inv;
            }
            #pragma unroll
            for (int j = 0; j < 4; j++) {
                float s = Mm[0*4+j] + Mm[1*4+j] + Mm[2*4+j] + Mm[3*4+j] + 1e-6f;
                float inv = 1.f / s;
                #pragma unroll
                for (int i = 0; i < 4; i++) Mm[i*4+j] *= inv;
            }
        }
        #pragma unroll
        for (int i = 0; i < 16; i++) sM[i] = Mm[i];
    }
    float ss = v.x*v.x + v.y*v.y + v.z*v.z + v.w*v.w;
    #pragma unroll
    for (int o = 16; o > 0; o >>= 1) ss += __shfl_xor_sync(0xffffffffu, ss, o);
    if ((tid & 31) == 0) red[tid >> 5] = ss;
    __syncthreads();
    if (tid == 0) {
        float tot = 0.f;
        #pragma unroll
        for (int i = 0; i < 8; i++) tot += red[i];
        s_scale = rsqrtf(tot * (1.0f / DMODEL) + EPS_RMS);
    }
    __syncthreads();
    float sc = s_scale;
    float4 wv = ((const float4*)w)[tid];
    float o0 = v.x*sc*wv.x, o1 = v.y*sc*wv.y, o2 = v.z*sc*wv.z, o3 = v.w*sc*wv.w;
    __nv_bfloat16 h0 = __float2bfloat16(o0), h1 = __float2bfloat16(o1);
    __nv_bfloat16 h2 = __float2bfloat16(o2), h3 = __float2bfloat16(o3);
    __nv_bfloat16 l0 = __float2bfloat16(o0 - __bfloat162float(h0));
    __nv_bfloat16 l1 = __float2bfloat16(o1 - __bfloat162float(h1));
    __nv_bfloat16 l2 = __float2bfloat16(o2 - __bfloat162float(h2));
    __nv_bfloat16 l3 = __float2bfloat16(o3 - __bfloat162float(h3));
    __nv_bfloat162* dh = (__nv_bfloat162*)(hi + (size_t)row * DMODEL);
    __nv_bfloat162* dl = (__nv_bfloat162*)(lo + (size_t)row * DMODEL);
    dh[tid*2]   = __halves2bfloat162(h0, h1);
    dh[tid*2+1] = __halves2bfloat162(h2, h3);
    dl[tid*2]   = __halves2bfloat162(l0, l1);
    dl[tid*2+1] = __halves2bfloat162(l2, l3);
    float hh0 = sr[tid], hh1 = sr[256 + tid], hh2 = sr[512 + tid], hh3 = sr[768 + tid];
    float* o = g_Hres + (size_t)row * DMODEL;
    #pragma unroll
    for (int j = 0; j < 4; j++)
        o[j*256 + tid] = sM[j*4+0]*hh0 + sM[j*4+1]*hh1 + sM[j*4+2]*hh2 + sM[j*4+3]*hh3;
}

// ---------------- RMS norm, fp16 output (head path) ----------------
__global__ void k_rms_f16(const float* __restrict__ w,
                          const float* __restrict__ src,
                          __half* __restrict__ dst) {
    int row = blockIdx.x, tid = threadIdx.x;
    float4 v = ((const float4*)(src + (size_t)row * DMODEL))[tid];
    float ss = v.x*v.x + v.y*v.y + v.z*v.z + v.w*v.w;
    #pragma unroll
    for (int o = 16; o > 0; o >>= 1) ss += __shfl_xor_sync(0xffffffffu, ss, o);
    __shared__ float red[8];
    __shared__ float s_scale;
    if ((tid & 31) == 0) red[tid >> 5] = ss;
    __syncthreads();
    if (tid == 0) {
        float tot = 0.f;
        #pragma unroll
        for (int i = 0; i < 8; i++) tot += red[i];
        s_scale = rsqrtf(tot * (1.0f / DMODEL) + EPS_RMS);
    }
    __syncthreads();
    float sc = s_scale;
    float4 wv = ((const float4*)w)[tid];
    __half2* dh = (__half2*)(dst + (size_t)row * DMODEL);
    dh[tid*2]   = __floats2half2_rn(v.x*sc*wv.x, v.y*sc*wv.y);
    dh[tid*2+1] = __floats2half2_rn(v.z*sc*wv.z, v.w*sc*wv.w);
}

// ---------------- scan phase 1: per-chunk local scan (dt/dtA inline) ----------------
__global__ void __launch_bounds__(64) k_scan1(const float* __restrict__ dt_bias,
                                              const float* __restrict__ A_log, int l) {
    int pblk = blockIdx.x, h = blockIdx.y;
    int b = blockIdx.z >> 5, c = blockIdx.z & 31;
    int tid = threadIdx.x;
    int p = pblk * 64 + tid;
    int t0 = c * TCH;
    float dtb = dt_bias[l*NHEADS + h];
    float Ah  = -expf(A_log[l*NHEADS + h]);
    __shared__ float sBC[2][128];
    float hs[64];
    #pragma unroll
    for (int n = 0; n < 64; n++) hs[n] = 0.f;
    float P = 1.f;

    float nb0, nb1, nx, ndt, ndA;
    {
        size_t r0 = (size_t)(b * L_SEQ + t0) * DPROJ;
        nb0 = g_zx[r0 + 2*DIN + NHEADS + h*128 + tid];
        nb1 = g_zx[r0 + 2*DIN + NHEADS + h*128 + 64 + tid];
        nx  = g_zx[r0 + DIN + h*PDIM + p];
        float v = g_zx[r0 + 2*DIN + h] + dtb;
        ndt = fmaxf(v, 0.f) + log1pf(expf(-fabsf(v)));
        ndA = expf(ndt * Ah);
    }
    sBC[0][tid] = nb0; sBC[0][64 + tid] = nb1;
    __syncthreads();

    for (int i = 0; i < TCH; i++) {
        int t = t0 + i;
        int buf = i & 1;
        float cx = nx, cdt = ndt, cdA = ndA;
        if (i + 1 < TCH) {
            size_t r1 = (size_t)(b * L_SEQ + t + 1) * DPROJ;
            nb0 = g_zx[r1 + 2*DIN + NHEADS + h*128 + tid];
            nb1 = g_zx[r1 + 2*DIN + NHEADS + h*128 + 64 + tid];
            nx  = g_zx[r1 + DIN + h*PDIM + p];
            float v = g_zx[r1 + 2*DIN + h] + dtb;
            ndt = fmaxf(v, 0.f) + log1pf(expf(-fabsf(v)));
            ndA = expf(ndt * Ah);
        }
        float ux = cdt * cx;
        float y0 = 0.f, y1 = 0.f, y2a = 0.f, y3 = 0.f;
        #pragma unroll
        for (int n4 = 0; n4 < 16; n4++) {
            float4 Bq = *(const float4*)&sBC[buf][n4 * 4];
            float4 Cq = *(const float4*)&sBC[buf][64 + n4 * 4];
            hs[n4*4+0] = fmaf(hs[n4*4+0], cdA, Bq.x * ux);
            hs[n4*4+1] = fmaf(hs[n4*4+1], cdA, Bq.y * ux);
            hs[n4*4+2] = fmaf(hs[n4*4+2], cdA, Bq.z * ux);
            hs[n4*4+3] = fmaf(hs[n4*4+3], cdA, Bq.w * ux);
            y0  = fmaf(Cq.x, hs[n4*4+0], y0);
            y1  = fmaf(Cq.y, hs[n4*4+1], y1);
            y2a = fmaf(Cq.z, hs[n4*4+2], y2a);
            y3  = fmaf(Cq.w, hs[n4*4+3], y3);
        }
        P *= cdA;
        if (pblk == 0 && tid == 0)
            g_cumA[(b * L_SEQ + t) * NHEADS + h] = P;
        g_ylocal[(size_t)(b * L_SEQ + t) * DIN + h * PDIM + p] =
            (y0 + y1) + (y2a + y3);
        sBC[buf ^ 1][tid] = nb0;
        sBC[buf ^ 1][64 + tid] = nb1;
        __syncthreads();
    }
    size_t sb = ((size_t)((b * NHEADS + h) * NCHUNK + c)) * DSTATE * PDIM;
    #pragma unroll
    for (int n = 0; n < 64; n++)
        g_S[sb + n * PDIM + p] = hs[n];
}

// ---------------- scan phase 2: inter-chunk recurrence (in place) ----------------
__global__ void k_scan2() {
    int bh = blockIdx.x;
    int b = bh >> 2, h = bh & 3;
    int idx = blockIdx.y * 256 + threadIdx.x;
    int n = idx >> 9, p = idx & 511;
    size_t base = ((size_t)bh * NCHUNK) * DSTATE * PDIM + n * PDIM + p;
    float prev = 0.f;
    for (int c = 0; c < NCHUNK; c++) {
        float Q = g_cumA[(b * L_SEQ + c * TCH + TCH - 1) * NHEADS + h];
        size_t o = base + (size_t)c * DSTATE * PDIM;
        float s = g_S[o];
        g_S[o] = prev;
        prev = fmaf(Q, prev, s);
    }
}

// ---------------- scan phase 3: correction + epilogue + bf16 split ----------------
__global__ void __launch_bounds__(256) k_scan3(const float* __restrict__ Dp, int l) {
    int c = blockIdx.x, h = blockIdx.y, b = blockIdx.z;
    int tid = threadIdx.x;
    __shared__ float sC[64][65];
    __shared__ float sP[64];
    __shared__ float shin[64][128];
    #pragma unroll
    for (int i = 0; i < 16; i++) {
        int e = tid + i * 256;
        int t = e >> 6, n = e & 63;
        int row = b * L_SEQ + c * TCH + t;
        sC[t][n] = g_zx[(size_t)row * DPROJ + 2*DIN + NHEADS + h*128 + 64 + n];
    }
    if (tid < 64)
        sP[tid] = g_cumA[(b * L_SEQ + c * TCH + tid) * NHEADS + h];
    float Dh = Dp[l * NHEADS + h];
    __syncthreads();

    size_t hb = ((size_t)((b * NHEADS + h) * NCHUNK + c)) * DSTATE * PDIM;
    int pl = tid & 127, tb = (tid >> 7) * 32;
    #pragma unroll
    for (int pt = 0; pt < 4; pt++) {
        int p0 = pt * 128;
        #pragma unroll
        for (int i = 0; i < 32; i++) {
            int e = tid + i * 256;
            int n = e >> 7, pp = e & 127;
            shin[n][pp] = g_S[hb + n * PDIM + p0 + pp];
        }
        __syncthreads();
        int p = p0 + pl;
        for (int tt = 0; tt < 32; tt++) {
            int t = tb + tt;
            float a0 = 0.f, a1 = 0.f;
            #pragma unroll
            for (int n = 0; n < 64; n += 2) {
                a0 = fmaf(sC[t][n],   shin[n][pl],   a0);
                a1 = fmaf(sC[t][n+1], shin[n+1][pl], a1);
            }
            int row = b * L_SEQ + c * TCH + t;
            size_t zo = (size_t)row * DPROJ;
            float x = g_zx[zo + DIN + h*PDIM + p];
            float z = g_zx[zo + h*PDIM + p];
            float yl = g_ylocal[(size_t)row * DIN + h*PDIM + p];
            float y = yl + sP[t] * (a0 + a1) + x * Dh;
            float sig = 1.f / (1.f + expf(-z));
            float out = y * (z * sig);
            size_t oi = (size_t)row * DIN + h * PDIM + p;
            __nv_bfloat16 oh = __float2bfloat16(out);
            g_Ahi[oi] = oh;
            g_Alo[oi] = __float2bfloat16(out - __bfloat162float(oh));
        }
        __syncthreads();
    }
}

// ================= shared GEMM helpers =================
#define KT      32
#define ASTRIDE (KT + 8)               /* 40 elems */
#define STAGE_A (128 * ASTRIDE)        /* 5120 elems */
#define GBN     128
#define GBSTR   (GBN + 8)              /* 136 */
#define GSTB    (KT * GBSTR)           /* 4352 elems */

__device__ __forceinline__ uint32_t smem_u32(const void* p) {
    return (uint32_t)__cvta_generic_to_shared(p);
}
__device__ __forceinline__ void cp16(uint32_t dst, const void* src) {
    asm volatile("cp.async.cg.shared.global [%0],[%1],16;\n" :: "r"(dst), "l"(src));
}
__device__ __forceinline__ void cp16z(uint32_t dst, const void* src, int bytes) {
    asm volatile("cp.async.cg.shared.global [%0],[%1],16,%2;\n" :: "r"(dst), "l"(src), "r"(bytes));
}
template<int G>
__device__ __forceinline__ void wgroup() {
    asm volatile("cp.async.wait_group %0;\n" :: "n"(G));
}
__device__ __forceinline__ void ldsm_x4(uint32_t* r, uint32_t a) {
    asm volatile("ldmatrix.sync.aligned.m8n8.x4.shared.b16 {%0,%1,%2,%3}, [%4];\n"
        : "=r"(r[0]), "=r"(r[1]), "=r"(r[2]), "=r"(r[3]) : "r"(a));
}
__device__ __forceinline__ void ldsm_x4t(uint32_t* r, uint32_t a) {
    asm volatile("ldmatrix.sync.aligned.m8n8.x4.trans.shared.b16 {%0,%1,%2,%3}, [%4];\n"
        : "=r"(r[0]), "=r"(r[1]), "=r"(r[2]), "=r"(r[3]) : "r"(a));
}
__device__ __forceinline__ void mma_bf16(float* c, const uint32_t* a, const uint32_t* b) {
    asm volatile(
        "mma.sync.aligned.m16n8k16.row.col.f32.bf16.bf16.f32 "
        "{%0,%1,%2,%3}, {%4,%5,%6,%7}, {%8,%9}, {%0,%1,%2,%3};\n"
        : "+f"(c[0]), "+f"(c[1]), "+f"(c[2]), "+f"(c[3])
        : "r"(a[0]), "r"(a[1]), "r"(a[2]), "r"(a[3]), "r"(b[0]), "r"(b[1]));
}
__device__ __forceinline__ void mma_f16(float* c, const uint32_t* a, const uint32_t* b) {
    asm volatile(
        "mma.sync.aligned.m16n8k16.row.col.f32.f16.f16.f32 "
        "{%0,%1,%2,%3}, {%4,%5,%6,%7}, {%8,%9}, {%0,%1,%2,%3};\n"
        : "+f"(c[0]), "+f"(c[1]), "+f"(c[2]), "+f"(c[3])
        : "r"(a[0]), "r"(a[1]), "r"(a[2]), "r"(a[3]), "r"(b[0]), "r"(b[1]));
}

// ================= bf16x3 GEMM (layers): 128x128 tile, 3 stages, 2 CTAs/SM =================
#define GSTAGES 3
#define GSELEMS (2*STAGE_A + 2*GSTB)           /* 18944 elems */
#define GSMEM   (GSTAGES * GSELEMS * 2)        /* 113664 B */

template<bool NGUARD>
__device__ __forceinline__ void load_stage(
    __nv_bfloat16* sb,
    const __nv_bfloat16* __restrict__ Ahi, const __nv_bfloat16* __restrict__ Alo,
    const __nv_bfloat16* __restrict__ Bhi, const __nv_bfloat16* __restrict__ Blo,
    int row0, int col0, int k0, int N, int Nld, int K, int tid)
{
    #pragma unroll
    for (int i = 0; i < 2; i++) {
        int c  = tid * 2 + i;
        int r  = c >> 2;
        int kc = (c & 3) * 8;
        size_t go = (size_t)(row0 + r) * K + k0 + kc;
        cp16(smem_u32(sb + r * ASTRIDE + kc),            Ahi + go);
        cp16(smem_u32(sb + STAGE_A + r * ASTRIDE + kc),  Alo + go);
    }
    #pragma unroll
    for (int i = 0; i < 2; i++) {
        int c   = tid + i * 256;
        int r   = c >> 4;
        int nc  = (c & 15) * 8;
        int col = col0 + nc;
        size_t go = (size_t)(k0 + r) * Nld + col;
        uint32_t dH = smem_u32(sb + 2*STAGE_A + r * GBSTR + nc);
        uint32_t dL = smem_u32(sb + 2*STAGE_A + GSTB + r * GBSTR + nc);
        if (!NGUARD) {
            cp16(dH, Bhi + go);
            cp16(dL, Blo + go);
        } else {
            int rem = N - col;
            if (rem >= 8) {
                cp16(dH, Bhi + go);
                cp16(dL, Blo + go);
            } else if (rem > 0) {
                cp16z(dH, Bhi + go, rem * 2);
                cp16z(dL, Blo + go, rem * 2);
            } else {
                uint4 z = make_uint4(0, 0, 0, 0);
                *(uint4*)(sb + 2*STAGE_A + r * GBSTR + nc) = z;
                *(uint4*)(sb + 2*STAGE_A + GSTB + r * GBSTR + nc) = z;
            }
        }
    }
}

template <bool RES>
__global__ void __launch_bounds__(256, 2) k_gemm3(
    const __nv_bfloat16* __restrict__ Ahi, const __nv_bfloat16* __restrict__ Alo,
    const __nv_bfloat16* __restrict__ Bhi, const __nv_bfloat16* __restrict__ Blo,
    const float* __restrict__ bias, const float* __restrict__ Rs,
    float* __restrict__ C, int M, int N, int Nld, int K)
{
    extern __shared__ __nv_bfloat16 smem[];
    int tid  = threadIdx.x;
    int row0 = blockIdx.x * 128, col0 = blockIdx.y * GBN;
    bool nguard = (col0 + GBN > N);
    int ktiles = K / KT;

    #pragma unroll
    for (int s = 0; s < GSTAGES - 1; s++) {
        __nv_bfloat16* sb = smem + s * GSELEMS;
        if (nguard) load_stage<true >(sb, Ahi, Alo, Bhi, Blo, row0, col0, s*KT, N, Nld, K, tid);
        else        load_stage<false>(sb, Ahi, Alo, Bhi, Blo, row0, col0, s*KT, N, Nld, K, tid);
        asm volatile("cp.async.commit_group;\n");
    }

    int lane = tid & 31, wid = tid >> 5;
    int wm = (wid & 1) * 64, wn = (wid >> 1) * 32;
    int a_r = lane & 15, a_c = (lane >> 4) * 8;
    int l8 = lane & 7, mat = lane >> 3;
    int brow = (mat & 1) * 8 + l8;
    int bcol = (mat >> 1) * 8;

    float acc[4][4][4];
    #pragma unroll
    for (int mt = 0; mt < 4; mt++)
        #pragma unroll
        for (int nt = 0; nt < 4; nt++)
            #pragma unroll
            for (int q = 0; q < 4; q++) acc[mt][nt][q] = 0.f;

    for (int kt = 0; kt < ktiles; kt++) {
        int rem = ktiles - 1 - kt;
        if (rem >= 1) wgroup<1>();
        else          wgroup<0>();
        __syncthreads();
        if (kt + GSTAGES - 1 < ktiles) {
            __nv_bfloat16* sb = smem + ((kt + GSTAGES - 1) % GSTAGES) * GSELEMS;
            int k0 = (kt + GSTAGES - 1) * KT;
            if (nguard) load_stage<true >(sb, Ahi, Alo, Bhi, Blo, row0, col0, k0, N, Nld, K, tid);
            else        load_stage<false>(sb, Ahi, Alo, Bhi, Blo, row0, col0, k0, N, Nld, K, tid);
            asm volatile("cp.async.commit_group;\n");
        }
        __nv_bfloat16* sb = smem + (kt % GSTAGES) * GSELEMS;
        __nv_bfloat16* sbB = sb + 2*STAGE_A;
        #pragma unroll
        for (int ks = 0; ks < 2; ks++) {
            uint32_t afh[4][4], afl[4][4];
            #pragma unroll
            for (int mt = 0; mt < 4; mt++) {
                int r = wm + mt*16 + a_r;
                ldsm_x4(afh[mt], smem_u32(sb + r*ASTRIDE + ks*16 + a_c));
                ldsm_x4(afl[mt], smem_u32(sb + STAGE_A + r*ASTRIDE + ks*16 + a_c));
            }
            #pragma unroll
            for (int np = 0; np < 2; np++) {
                uint32_t bh[4], bl[4];
                int boff = (ks*16 + brow)*GBSTR + wn + np*16 + bcol;
                ldsm_x4t(bh, smem_u32(sbB + boff));
                ldsm_x4t(bl, smem_u32(sbB + GSTB + boff));
                // term-major issue order: same-accumulator reuse distance = 8 mma
                #pragma unroll
                for (int mt = 0; mt < 4; mt++) mma_bf16(acc[mt][np*2],   afh[mt], bh);
                #pragma unroll
                for (int mt = 0; mt < 4; mt++) mma_bf16(acc[mt][np*2+1], afh[mt], bh + 2);
                #pragma unroll
                for (int mt = 0; mt < 4; mt++) mma_bf16(acc[mt][np*2],   afh[mt], bl);
                #pragma unroll
                for (int mt = 0; mt < 4; mt++) mma_bf16(acc[mt][np*2+1], afh[mt], bl + 2);
                #pragma unroll
                for (int mt = 0; mt < 4; mt++) mma_bf16(acc[mt][np*2],   afl[mt], bh);
                #pragma unroll
                for (int mt = 0; mt < 4; mt++) mma_bf16(acc[mt][np*2+1], afl[mt], bh + 2);
            }
        }
    }

    #pragma unroll
    for (int mt = 0; mt < 4; mt++) {
        int r0 = row0 + wm + mt*16 + (lane >> 2);
        int r1 = r0 + 8;
        #pragma unroll
        for (int nt = 0; nt < 4; nt++) {
            int c0 = col0 + wn + nt*8 + (lane & 3)*2;
            float* a = acc[mt][nt];
            if (c0 < N) {
                float v0 = a[0] + bias[c0];
                float v2 = a[2] + bias[c0];
                if (RES) { v0 += Rs[(size_t)r0*N + c0]; v2 += Rs[(size_t)r1*N + c0]; }
                C[(size_t)r0*N + c0] = v0;
                C[(size_t)r1*N + c0] = v2;
            }
            if (c0 + 1 < N) {
                float v1 = a[1] + bias[c0+1];
                float v3 = a[3] + bias[c0+1];
                if (RES) { v1 += Rs[(size_t)r0*N + c0+1]; v3 += Rs[(size_t)r1*N + c0+1]; }
                C[(size_t)r0*N + c0+1] = v1;
                C[(size_t)r1*N + c0+1] = v3;
            }
        }
    }
}

// ================= fp16x1 GEMM (head): 128x128 tile, KT=64, 3 stages, 2 CTAs/SM =================
#define HKT     64
#define HASTR   (HKT + 8)              /* 72 elems */
#define HSTGA   (128 * HASTR)          /* 9216 elems */
#define HSTB    (HKT * GBSTR)          /* 8704 elems */
#define HSELEMS (HSTGA + HSTB)         /* 17920 elems = 35840 B */
#define HSTAGES 3
#define HSMEM   (HSTAGES * HSELEMS * 2) /* 107520 B */

__device__ __forceinline__ void load_stage_h(
    __half* sb,
    const __half* __restrict__ A, const __half* __restrict__ B,
    int row0, int col0, int k0, int N, int K, int tid)
{
    // A: 128 rows x 64 k = 1024 chunks of 8, 4/thread
    #pragma unroll
    for (int i = 0; i < 4; i++) {
        int c  = tid + i * 256;
        int r  = c >> 3;
        int kc = (c & 7) * 8;
        cp16(smem_u32(sb + r * HASTR + kc), A + (size_t)(row0 + r) * K + k0 + kc);
    }
    // B: 64 k-rows x 128 n = 1024 chunks of 8, 4/thread
    #pragma unroll
    for (int i = 0; i < 4; i++) {
        int c   = tid + i * 256;
        int r   = c >> 4;
        int nc  = (c & 15) * 8;
        size_t go = (size_t)(k0 + r) * N + col0 + nc;
        cp16(smem_u32(sb + HSTGA + r * GBSTR + nc), B + go);
    }
}

__global__ void __launch_bounds__(256, 2) k_gemm1h(
    const __half* __restrict__ A, const __half* __restrict__ B,
    const float* __restrict__ bias,
    float* __restrict__ C, int M, int N, int K)
{
    extern __shared__ __half hsmem[];
    int tid  = threadIdx.x;
    int row0 = blockIdx.x * 128, col0 = blockIdx.y * GBN;
    int ktiles = K / HKT;   /* 16 */

    #pragma unroll
    for (int s = 0; s < HSTAGES - 1; s++) {
        load_stage_h(hsmem + s * HSELEMS, A, B, row0, col0, s*HKT, N, K, tid);
        asm volatile("cp.async.commit_group;\n");
    }

    int lane = tid & 31, wid = tid >> 5;
    int wm = (wid & 1) * 64, wn = (wid >> 1) * 32;
    int a_r = lane & 15, a_c = (lane >> 4) * 8;
    int l8 = lane & 7, mat = lane >> 3;
    int brow = (mat & 1) * 8 + l8;
    int bcol = (mat >> 1) * 8;

    float acc[4][4][4];
    #pragma unroll
    for (int mt = 0; mt < 4; mt++)
        #pragma unroll
        for (int nt = 0; nt < 4; nt++)
            #pragma unroll
            for (int q = 0; q < 4; q++) acc[mt][nt][q] = 0.f;

    for (int kt = 0; kt < ktiles; kt++) {
        int rem = ktiles - 1 - kt;
        if (rem >= 1) wgroup<1>();
        else          wgroup<0>();
        __syncthreads();
        if (kt + HSTAGES - 1 < ktiles) {
            load_stage_h(hsmem + ((kt + HSTAGES - 1) % HSTAGES) * HSELEMS,
                         A, B, row0, col0, (kt + HSTAGES - 1) * HKT, N, K, tid);
            asm volatile("cp.async.commit_group;\n");
        }
        __half* sb  = hsmem + (kt % HSTAGES) * HSELEMS;
        __half* sbB = sb + HSTGA;
        #pragma unroll
        for (int ks = 0; ks < 4; ks++) {
            uint32_t af[4][4];
            #pragma unroll
            for (int mt = 0; mt < 4; mt++) {
                int r = wm + mt*16 + a_r;
                ldsm_x4(af[mt], smem_u32(sb + r*HASTR + ks*16 + a_c));
            }
            #pragma unroll
            for (int np = 0; np < 2; np++) {
                uint32_t bb[4];
                int boff = (ks*16 + brow)*GBSTR + wn + np*16 + bcol;
                ldsm_x4t(bb, smem_u32(sbB + boff));
                #pragma unroll
                for (int mt = 0; mt < 4; mt++) {
                    mma_f16(acc[mt][np*2],   af[mt], bb);
                    mma_f16(acc[mt][np*2+1], af[mt], bb + 2);
                }
            }
        }
    }

    #pragma unroll
    for (int mt = 0; mt < 4; mt++) {
        int r0 = row0 + wm + mt*16 + (lane >> 2);
        int r1 = r0 + 8;
        #pragma unroll
        for (int nt = 0; nt < 4; nt++) {
            int c0 = col0 + wn + nt*8 + (lane & 3)*2;
            float* a = acc[mt][nt];
            float b0 = bias[c0], b1 = bias[c0+1];
            C[(size_t)r0*N + c0]     = a[0] + b0;
            C[(size_t)r0*N + c0 + 1] = a[1] + b1;
            C[(size_t)r1*N + c0]     = a[2] + b0;
            C[(size_t)r1*N + c0 + 1] = a[3] + b1;
        }
    }
}

// ---------------- host orchestration ----------------
extern "C" void kernel_launch(void* const* d_in, const int* in_sizes, int n_in,
                              void* d_out, int out_size) {
    const int*   tokens  = (const int*)  d_in[0];
    const float* embed   = (const float*)d_in[1];
    const float* norm_w  = (const float*)d_in[2];
    const float* Wi      = (const float*)d_in[3];
    const float* bi      = (const float*)d_in[4];
    const float* A_log   = (const float*)d_in[5];
    const float* Dp      = (const float*)d_in[6];
    const float* dt_bias = (const float*)d_in[7];
    const float* Wo      = (const float*)d_in[8];
    const float* bo      = (const float*)d_in[9];
    const float* mixl    = (const float*)d_in[10];
    const float* norm_f  = (const float*)d_in[11];
    const float* headW   = (const float*)d_in[12];
    const float* headb   = (const float*)d_in[13];
    float* out = (float*)d_out;

    cudaFuncSetAttribute((const void*)k_gemm3<false>, cudaFuncAttributeMaxDynamicSharedMemorySize, GSMEM);
    cudaFuncSetAttribute((const void*)k_gemm3<true >, cudaFuncAttributeMaxDynamicSharedMemorySize, GSMEM);
    cudaFuncSetAttribute((const void*)k_gemm1h,       cudaFuncAttributeMaxDynamicSharedMemorySize, HSMEM);

    void *pH, *pHres, *pzx, *pAhi, *pAlo, *pWiHi, *pWiLo, *pWoHi, *pWoLo, *pHB;
    cudaGetSymbolAddress(&pH,    g_H);
    cudaGetSymbolAddress(&pHres, g_Hres);
    cudaGetSymbolAddress(&pzx,   g_zx);
    cudaGetSymbolAddress(&pAhi,  g_Ahi);
    cudaGetSymbolAddress(&pAlo,  g_Alo);
    cudaGetSymbolAddress(&pWiHi, g_WiHi);
    cudaGetSymbolAddress(&pWiLo, g_WiLo);
    cudaGetSymbolAddress(&pWoHi, g_WoHi);
    cudaGetSymbolAddress(&pWoLo, g_WoLo);
    cudaGetSymbolAddress(&pHB,   g_HB);
    float* fH    = (float*)pH;
    float* fHres = (float*)pHres;
    float* fzx   = (float*)pzx;
    __nv_bfloat16* Ahi  = (__nv_bfloat16*)pAhi;
    __nv_bfloat16* Alo  = (__nv_bfloat16*)pAlo;
    __nv_bfloat16* WiHi = (__nv_bfloat16*)pWiHi;
    __nv_bfloat16* WiLo = (__nv_bfloat16*)pWiLo;
    __nv_bfloat16* WoHi = (__nv_bfloat16*)pWoHi;
    __nv_bfloat16* WoLo = (__nv_bfloat16*)pWoLo;
    __half* hB = (__half*)pHB;
    __half* hA = (__half*)pAhi;   // head A reuses g_Ahi storage as fp16

    k_embed<<<NROWS, 256>>>(tokens, embed);
    k_splitAll<<<WI_BLKS + WO_BLKS + HD_BLKS, 256>>>(Wi, Wo, headW);

    for (int l = 0; l < NLAYERS; l++) {
        k_pre<<<NROWS, 256>>>(mixl + l * 16, norm_w + (size_t)l * DMODEL, Ahi, Alo);
        k_gemm3<false><<<dim3(NROWS / 128, (DPROJ + GBN - 1) / GBN), 256, GSMEM>>>(
            Ahi, Alo,
            WiHi + (size_t)l * DMODEL * NPAD_I, WiLo + (size_t)l * DMODEL * NPAD_I,
            bi + (size_t)l * DPROJ, nullptr,
            fzx, NROWS, DPROJ, NPAD_I, DMODEL);
        k_scan1<<<dim3(8, NHEADS, BATCH * NCHUNK), 64>>>(dt_bias, A_log, l);
        k_scan2<<<dim3(BATCH * NHEADS, 128), 256>>>();
        k_scan3<<<dim3(NCHUNK, NHEADS, BATCH), 256>>>(Dp, l);
        k_gemm3<true><<<dim3(NROWS / 128, DMODEL / GBN), 256, GSMEM>>>(
            Ahi, Alo,
            WoHi + (size_t)l * DIN * DMODEL, WoLo + (size_t)l * DIN * DMODEL,
            bo + (size_t)l * DMODEL, fHres,
            fH, NROWS, DMODEL, DMODEL, DIN);
    }

    // head: plain fp16, KT=64, 3 stages
    k_rms_f16<<<NROWS, 256>>>(norm_f, fH, hA);
    k_gemm1h<<<dim3(NROWS / 128, VOCAB / GBN), 256, HSMEM>>>(
        hA, hB, headb, out, NROWS, VOCAB, DMODEL);
}